// round 7
// baseline (speedup 1.0000x reference)
#include <cuda_runtime.h>
#include <cuda_bf16.h>
#include <cstdint>
#include <math.h>

#define BSZ 256
#define TT  64
#define AA  32
#define HH  512
#define EE  32

// -------- device scratch (allocation-free) --------
__device__ __align__(256) __nv_bfloat16 g_B3[EE][HH][1024]; // [e][n][hi(512)|lo(512)]
__device__ __align__(256) __nv_bfloat16 g_A3[BSZ][TT][1024]; // x2 [hi(512)|lo(512)]
__device__ __align__(256) float g_F[EE][AA][HH];   // fused W1@W2a
__device__ __align__(256) float g_c[EE][HH];       // b1@W2a + b2
__device__ __align__(256) float g_tauf[BSZ][512];  // sinusoidal tau (fp32)
__device__ __align__(256) float g_tc[BSZ][HH];     // tau @ W2tau
__device__ int2 g_pairs[160];
__device__ int  g_npairs;
__device__ int  g_scnt[EE];
__device__ int  g_slist[EE][BSZ];

// -------- helpers --------
__device__ __forceinline__ uint32_t smem_u32(const void* p){
    uint32_t a;
    asm("{ .reg .u64 t; cvta.to.shared.u64 t, %1; cvt.u32.u64 %0, t; }" : "=r"(a) : "l"(p));
    return a;
}
__device__ __forceinline__ unsigned pk(__nv_bfloat16 a, __nv_bfloat16 b){
    unsigned short x = *reinterpret_cast<unsigned short*>(&a);
    unsigned short y = *reinterpret_cast<unsigned short*>(&b);
    return (unsigned)x | ((unsigned)y << 16);
}

#define CP_ASYNC16(dst, src) \
    asm volatile("cp.async.cg.shared.global [%0], [%1], 16;" :: "r"(dst), "l"(src))
#define CP_COMMIT() asm volatile("cp.async.commit_group;" ::: "memory")
#define CP_WAIT0()  asm volatile("cp.async.wait_group 0;" ::: "memory")
#define CP_WAIT1()  asm volatile("cp.async.wait_group 1;" ::: "memory")

#define LDSM_X4(r, addr) \
    asm volatile("ldmatrix.sync.aligned.m8n8.x4.shared.b16 {%0,%1,%2,%3}, [%4];" \
        : "=r"((r)[0]), "=r"((r)[1]), "=r"((r)[2]), "=r"((r)[3]) : "r"(addr))

#define MMA16816(d, a, b0, b1) \
    asm volatile("mma.sync.aligned.m16n8k16.row.col.f32.bf16.bf16.f32 " \
        "{%0,%1,%2,%3}, {%4,%5,%6,%7}, {%8,%9}, {%0,%1,%2,%3};" \
        : "+f"((d)[0]), "+f"((d)[1]), "+f"((d)[2]), "+f"((d)[3]) \
        : "r"((a)[0]), "r"((a)[1]), "r"((a)[2]), "r"((a)[3]), "r"(b0), "r"(b1))

// ---------------------------------------------------------------------------
// W3 conversion: (E,512,512) fp32 -> g_B3[e][n][hi(512)|lo(512)] (transposed)
// ---------------------------------------------------------------------------
__global__ __launch_bounds__(256) void conv_w3(const float* __restrict__ W)
{
    __shared__ float sm[32][33];
    const int kt = blockIdx.x, nt = blockIdx.y, e = blockIdx.z;
    const int k0 = kt * 32, n0 = nt * 32;
    const int tid = threadIdx.x;
    #pragma unroll
    for (int i = 0; i < 4; i++) {
        int idx = tid + i * 256;
        int kk = idx >> 5, nn = idx & 31;
        sm[kk][nn] = W[((size_t)e * HH + k0 + kk) * HH + n0 + nn];
    }
    __syncthreads();
    const int n = tid >> 3, g = tid & 7;
    __nv_bfloat16 hi[4], lo[4];
    #pragma unroll
    for (int j = 0; j < 4; j++) {
        float x = sm[g * 4 + j][n];
        hi[j] = __float2bfloat16_rn(x);
        lo[j] = __float2bfloat16_rn(x - __bfloat162float(hi[j]));
    }
    __nv_bfloat16* dst = &g_B3[e][n0 + n][k0 + g * 4];
    *reinterpret_cast<uint2*>(dst)       = make_uint2(pk(hi[0], hi[1]), pk(hi[2], hi[3]));
    *reinterpret_cast<uint2*>(dst + 512) = make_uint2(pk(lo[0], lo[1]), pk(lo[2], lo[3]));
}

// ---------------------------------------------------------------------------
// Pairing + per-expert sample lists
// ---------------------------------------------------------------------------
__global__ void k_pairs(const int* __restrict__ cat_ids)
{
    int e = threadIdx.x;  // 32 threads
    int cnt = 0;
    for (int s = 0; s < BSZ; s++) cnt += (cat_ids[s] == e);
    g_scnt[e] = cnt;
    int np = (cnt + 1) >> 1;
    int inc = np;
    for (int d = 1; d < 32; d <<= 1) {
        int v = __shfl_up_sync(0xffffffffu, inc, d);
        if (e >= d) inc += v;
    }
    int off = inc - np;
    if (e == 31) g_npairs = off + np;
    int a = -1, w = off, li = 0;
    for (int s = 0; s < BSZ; s++) {
        if (cat_ids[s] == e) {
            g_slist[e][li++] = s;
            if (a < 0) a = s;
            else { g_pairs[w++] = make_int2(a, s); a = -1; }
        }
    }
    if (a >= 0) g_pairs[w++] = make_int2(a, a);
}

// ---------------------------------------------------------------------------
// kF: F[e] = W1[e] @ W2a[e]  (32x512 @ 512x512), c[e] = b1@W2a + b2. fp32.
// grid (16 n-chunks of 32, EE), 256 threads. W1[e] staged in 64KB dyn smem.
// ---------------------------------------------------------------------------
__global__ __launch_bounds__(256) void kF(
    const float* __restrict__ W1, const float* __restrict__ W2,
    const float* __restrict__ b1, const float* __restrict__ b2)
{
    const int e = blockIdx.y;
    const int n0 = blockIdx.x * 32;
    const int tid = threadIdx.x;
    extern __shared__ float sW1[]; // 32*512 floats
    const float* W1e = W1 + (size_t)e * AA * HH;
    for (int i = tid; i < AA * HH / 4; i += 256)
        reinterpret_cast<float4*>(sW1)[i] = reinterpret_cast<const float4*>(W1e)[i];
    __syncthreads();

    const int n = tid & 31, a0 = (tid >> 5) * 4;
    const float* W2a = W2 + (size_t)e * 1024 * HH + n0 + n;
    float acc[4] = {0.f, 0.f, 0.f, 0.f};
    #pragma unroll 4
    for (int h = 0; h < HH; h++) {
        float wv = W2a[(size_t)h * HH];
        #pragma unroll
        for (int i = 0; i < 4; i++) acc[i] += sW1[(a0 + i) * HH + h] * wv;
    }
    #pragma unroll
    for (int i = 0; i < 4; i++) g_F[e][a0 + i][n0 + n] = acc[i];

    // c[n] = b2[n] + sum_h b1[h] * W2a[h][n]
    __shared__ float sred[256];
    const int hq = tid >> 5;
    float p = 0.f;
    #pragma unroll 4
    for (int h = hq * 64; h < hq * 64 + 64; h++)
        p += b1[e * HH + h] * W2a[(size_t)h * HH];
    sred[tid] = p;
    __syncthreads();
    if (hq == 0) {
        float sum = 0.f;
        #pragma unroll
        for (int q = 0; q < 8; q++) sum += sred[q * 32 + tid];
        g_c[e][n0 + n] = sum + b2[e * HH + n0 + n];
    }
}

// ---------------------------------------------------------------------------
// k_tau: sinusoidal embedding per sample (fp32)
// ---------------------------------------------------------------------------
__global__ void k_tau(const int* __restrict__ timesteps)
{
    int s = blockIdx.x, tid = threadIdx.x;
    float tval = (float)timesteps[s];
    float f = tval * expf(-(float)tid * (9.210340371976184f / 256.0f));
    g_tauf[s][tid]       = sinf(f);
    g_tauf[s][256 + tid] = cosf(f);
}

// ---------------------------------------------------------------------------
// k_tauc: tc[s] = tau[s] @ W2tau[e]. grid (4 n-chunks of 128, EE).
// Expert-grouped: W2tau chunk stays hot in L1/L2 across the expert's samples.
// ---------------------------------------------------------------------------
__global__ __launch_bounds__(256) void k_tauc(const float* __restrict__ W2)
{
    const int e = blockIdx.y, n0 = blockIdx.x * 128, tid = threadIdx.x;
    const int cnt = g_scnt[e];
    const int n = tid & 127, kh = tid >> 7;
    __shared__ float stau[512];
    __shared__ float sred[256];
    const float* W2t = W2 + (size_t)e * 1024 * HH + (size_t)(512 + kh * 256) * HH + n0 + n;
    for (int i = 0; i < cnt; i++) {
        int s = g_slist[e][i];
        stau[tid]       = g_tauf[s][tid];
        stau[256 + tid] = g_tauf[s][256 + tid];
        __syncthreads();
        float p = 0.f;
        #pragma unroll 4
        for (int k = 0; k < 256; k++)
            p += stau[kh * 256 + k] * W2t[(size_t)k * HH];
        sred[tid] = p;
        __syncthreads();
        if (kh == 0) g_tc[s][n0 + n] = sred[n] + sred[128 + n];
        __syncthreads();
    }
}

// ---------------------------------------------------------------------------
// k2: y2 = actions@F[e] (K=32) + tc + c; x2 = swish(y2) -> hi/lo bf16 in g_A3
// grid (BSZ, 2 t-halves), 256 threads; each thread owns 2 output columns.
// ---------------------------------------------------------------------------
__global__ __launch_bounds__(256) void k2_mid(
    const float* __restrict__ actions, const int* __restrict__ cat_ids)
{
    const int s = blockIdx.x, tid = threadIdx.x;
    const int tbase = blockIdx.y * 32;
    const int e = cat_ids[s];
    __shared__ float sA[32][36];

    const float* Ab = actions + ((size_t)s * TT + tbase) * AA;
    {
        int row = tid >> 3, c4 = tid & 7;
        float4 v = *reinterpret_cast<const float4*>(&Ab[row * AA + c4 * 4]);
        *reinterpret_cast<float4*>(&sA[row][c4 * 4]) = v;
    }
    __syncthreads();

    const int h0 = 2 * tid;
    float2 w[AA];
    #pragma unroll
    for (int k = 0; k < AA; k++)
        w[k] = *reinterpret_cast<const float2*>(&g_F[e][k][h0]);
    float2 tc = *reinterpret_cast<const float2*>(&g_tc[s][h0]);
    float2 cc = *reinterpret_cast<const float2*>(&g_c[e][h0]);
    const float base0 = tc.x + cc.x, base1 = tc.y + cc.y;

    for (int tl = 0; tl < 32; tl++) {
        float a0 = base0, a1 = base1;
        #pragma unroll
        for (int k = 0; k < AA; k++) {
            float av = sA[tl][k];
            a0 += av * w[k].x; a1 += av * w[k].y;
        }
        a0 = a0 * (1.f / (1.f + expf(-a0)));
        a1 = a1 * (1.f / (1.f + expf(-a1)));
        __nv_bfloat16 hh0 = __float2bfloat16_rn(a0), hh1 = __float2bfloat16_rn(a1);
        __nv_bfloat16 ll0 = __float2bfloat16_rn(a0 - __bfloat162float(hh0));
        __nv_bfloat16 ll1 = __float2bfloat16_rn(a1 - __bfloat162float(hh1));
        __nv_bfloat16* row = &g_A3[s][tbase + tl][0];
        *reinterpret_cast<unsigned*>(row + h0)       = pk(hh0, hh1);
        *reinterpret_cast<unsigned*>(row + 512 + h0) = pk(ll0, ll1);
    }
}

// ---------------------------------------------------------------------------
// Layer-3 GEMM (mma.sync, fused 3-term hi/lo). M=128 (sample pair), N=256.
// Stage: Ahi@0(16K)|Alo@16K|Bhi@32K(32K)|Blo@64K(32K) = 96KB, 2 stages.
// ---------------------------------------------------------------------------
#define STAGE_BYTES 98304
#define GSMEM (2 * STAGE_BYTES + 1024)

__global__ __launch_bounds__(256, 1) void gemm3(
    const float* __restrict__ bias, const int* __restrict__ cat_ids,
    float* __restrict__ out)
{
    constexpr int KP  = 512;
    constexpr int TPC = KP / 64;

    const int mt_blk = blockIdx.y;
    if (mt_blk >= g_npairs) return;
    const int n0 = blockIdx.x * 256;
    const int2 pr = g_pairs[mt_blk];
    const int s0 = pr.x, s1 = pr.y;
    const int e  = cat_ids[s0];

    extern __shared__ char smem[];
    const uint32_t sb = (smem_u32(smem) + 127) & ~127u;

    const int tid  = threadIdx.x;
    const int wid  = tid >> 5;
    const int lane = tid & 31;
    const int mWarp = (wid >> 2) * 64;
    const int nWarp = (wid & 3) * 64;

    const __nv_bfloat16* aRow[4]; uint32_t dAo[4];
    #pragma unroll
    for (int i = 0; i < 4; i++) {
        int idx = tid + 256 * i;
        int r = idx >> 3, sg = idx & 7;
        int samp = (r < 64) ? s0 : s1;
        aRow[i] = &g_A3[samp][r & 63][0] + sg * 8;
        dAo[i]  = (uint32_t)(r * 128 + ((sg * 16) ^ ((r & 7) * 16)));
    }
    const __nv_bfloat16* bRow[8]; uint32_t dBo[8];
    #pragma unroll
    for (int i = 0; i < 8; i++) {
        int idx = tid + 256 * i;
        int r = idx >> 3, sg = idx & 7;
        bRow[i] = &g_B3[e][n0 + r][0] + sg * 8;
        dBo[i]  = (uint32_t)(r * 128 + ((sg * 16) ^ ((r & 7) * 16)));
    }

    auto issue = [&](int c) {
        int pkk = c * 64;
        uint32_t sof = sb + (uint32_t)(c & 1) * STAGE_BYTES;
        #pragma unroll
        for (int i = 0; i < 4; i++) {
            CP_ASYNC16(sof + dAo[i],         aRow[i] + pkk);       // Ahi
            CP_ASYNC16(sof + 16384 + dAo[i], aRow[i] + KP + pkk);  // Alo
        }
        #pragma unroll
        for (int i = 0; i < 8; i++) {
            CP_ASYNC16(sof + 32768 + dBo[i], bRow[i] + pkk);       // Bhi
            CP_ASYNC16(sof + 65536 + dBo[i], bRow[i] + KP + pkk);  // Blo
        }
        CP_COMMIT();
    };

    const uint32_t maskk = (lane & 7) * 16;
    const uint32_t aRowB = (uint32_t)(mWarp + (lane & 7) + ((lane & 8) ? 8 : 0)) * 128;
    const uint32_t kextA = (lane & 16) ? 16 : 0;
    const uint32_t bRowB = (uint32_t)((nWarp + (lane & 7) + ((lane & 16) ? 8 : 0)) * 128);
    const uint32_t kextB = (lane & 8) ? 16 : 0;

    float acc[4][8][4];
    #pragma unroll
    for (int m = 0; m < 4; m++)
        #pragma unroll
        for (int j = 0; j < 8; j++)
            #pragma unroll
            for (int q = 0; q < 4; q++) acc[m][j][q] = 0.f;

    issue(0);

    for (int c = 0; c < TPC; c++) {
        __syncthreads();
        if (c + 1 < TPC) { issue(c + 1); CP_WAIT1(); } else { CP_WAIT0(); }
        __syncthreads();

        const uint32_t stb = sb + (uint32_t)(c & 1) * STAGE_BYTES;
        #pragma unroll
        for (int ks = 0; ks < 4; ks++) {
            const uint32_t kA = (uint32_t)(ks * 32 + kextA) ^ maskk;
            const uint32_t kB = (uint32_t)(ks * 32 + kextB) ^ maskk;
            uint32_t a[4][4], b[4][4], c2[4][4];
            #pragma unroll
            for (int m = 0; m < 4; m++)
                LDSM_X4(a[m], stb + aRowB + m * 2048 + kA);
            #pragma unroll
            for (int nt = 0; nt < 4; nt++)
                LDSM_X4(b[nt], stb + 32768 + bRowB + nt * 2048 + kB);
            #pragma unroll
            for (int m = 0; m < 4; m++)
                #pragma unroll
                for (int j = 0; j < 8; j++)
                    MMA16816(acc[m][j], a[m], b[j >> 1][(j & 1) * 2], b[j >> 1][(j & 1) * 2 + 1]);
            #pragma unroll
            for (int m = 0; m < 4; m++)
                LDSM_X4(c2[m], stb + 16384 + aRowB + m * 2048 + kA);
            #pragma unroll
            for (int m = 0; m < 4; m++)
                #pragma unroll
                for (int j = 0; j < 8; j++)
                    MMA16816(acc[m][j], c2[m], b[j >> 1][(j & 1) * 2], b[j >> 1][(j & 1) * 2 + 1]);
            #pragma unroll
            for (int nt = 0; nt < 4; nt++)
                LDSM_X4(c2[nt], stb + 65536 + bRowB + nt * 2048 + kB);
            #pragma unroll
            for (int m = 0; m < 4; m++)
                #pragma unroll
                for (int j = 0; j < 8; j++)
                    MMA16816(acc[m][j], a[m], c2[j >> 1][(j & 1) * 2], c2[j >> 1][(j & 1) * 2 + 1]);
        }
    }

    const float* biasE = bias + e * HH;
    const int sampW = (mWarp < 64) ? s0 : s1;
    #pragma unroll
    for (int m = 0; m < 4; m++) {
        int rloc = mWarp + m * 16 + (lane >> 2);
        int t0 = rloc & 63, t1 = (rloc + 8) & 63;
        #pragma unroll
        for (int j = 0; j < 8; j++) {
            int cidx = n0 + nWarp + j * 8 + (lane & 3) * 2;
            float2 bv = *reinterpret_cast<const float2*>(&biasE[cidx]);
            float* p0 = out + ((size_t)sampW * TT + t0) * HH + cidx;
            float* p1 = out + ((size_t)sampW * TT + t1) * HH + cidx;
            *reinterpret_cast<float2*>(p0) = make_float2(acc[m][j][0] + bv.x, acc[m][j][1] + bv.y);
            *reinterpret_cast<float2*>(p1) = make_float2(acc[m][j][2] + bv.x, acc[m][j][3] + bv.y);
        }
    }
}

// ---------------------------------------------------------------------------
extern "C" void kernel_launch(void* const* d_in, const int* in_sizes, int n_in,
                              void* d_out, int out_size)
{
    const float* actions   = (const float*)d_in[0];
    const int*   timesteps = (const int*)  d_in[1];
    const int*   cat_ids   = (const int*)  d_in[2];
    const float* W1        = (const float*)d_in[3];
    const float* b1        = (const float*)d_in[4];
    const float* W2        = (const float*)d_in[5];
    const float* b2        = (const float*)d_in[6];
    const float* W3        = (const float*)d_in[7];
    const float* b3        = (const float*)d_in[8];
    float* out = (float*)d_out;

    cudaFuncSetAttribute(gemm3, cudaFuncAttributeMaxDynamicSharedMemorySize, GSMEM);
    cudaFuncSetAttribute(kF, cudaFuncAttributeMaxDynamicSharedMemorySize, 65536);

    conv_w3<<<dim3(16, 16, EE), 256>>>(W3);
    k_pairs<<<1, 32>>>(cat_ids);
    kF<<<dim3(16, EE), 256, 65536>>>(W1, W2, b1, b2);
    k_tau<<<BSZ, 256>>>(timesteps);
    k_tauc<<<dim3(4, EE), 256>>>(W2);
    k2_mid<<<dim3(BSZ, 2), 256>>>(actions, cat_ids);
    gemm3<<<dim3(2, 144), 256, GSMEM>>>(b3, cat_ids, out);
}

// round 12
// speedup vs baseline: 1.4119x; 1.4119x over previous
#include <cuda_runtime.h>
#include <cuda_bf16.h>
#include <cstdint>
#include <math.h>

#define BSZ 256
#define TT  64
#define AA  32
#define HH  512
#define EE  32

// -------- device scratch (allocation-free) --------
__device__ __align__(256) __nv_bfloat16 g_B3[EE][HH][1024]; // [e][n][hi(512)|lo(512)]
__device__ __align__(256) __nv_bfloat16 g_A3[BSZ][TT][1024]; // x2 [hi(512)|lo(512)]
__device__ __align__(256) float g_F[EE][AA][HH];   // fused W1@W2a
__device__ __align__(256) float g_c[EE][HH];       // b1@W2a + b2
__device__ __align__(256) float g_tc[BSZ][HH];     // tau @ W2tau
__device__ int2 g_pairs[160];
__device__ int  g_npairs;
__device__ int  g_scnt[EE];
__device__ int  g_slist[EE][BSZ];

// -------- helpers --------
__device__ __forceinline__ uint32_t smem_u32(const void* p){
    uint32_t a;
    asm("{ .reg .u64 t; cvta.to.shared.u64 t, %1; cvt.u32.u64 %0, t; }" : "=r"(a) : "l"(p));
    return a;
}
__device__ __forceinline__ unsigned pk(__nv_bfloat16 a, __nv_bfloat16 b){
    unsigned short x = *reinterpret_cast<unsigned short*>(&a);
    unsigned short y = *reinterpret_cast<unsigned short*>(&b);
    return (unsigned)x | ((unsigned)y << 16);
}

#define CP_ASYNC16(dst, src) \
    asm volatile("cp.async.cg.shared.global [%0], [%1], 16;" :: "r"(dst), "l"(src))
#define CP_COMMIT() asm volatile("cp.async.commit_group;" ::: "memory")
#define CP_WAIT0()  asm volatile("cp.async.wait_group 0;" ::: "memory")
#define CP_WAIT1()  asm volatile("cp.async.wait_group 1;" ::: "memory")

#define LDSM_X4(r, addr) \
    asm volatile("ldmatrix.sync.aligned.m8n8.x4.shared.b16 {%0,%1,%2,%3}, [%4];" \
        : "=r"((r)[0]), "=r"((r)[1]), "=r"((r)[2]), "=r"((r)[3]) : "r"(addr))

#define MMA16816(d, a, b0, b1) \
    asm volatile("mma.sync.aligned.m16n8k16.row.col.f32.bf16.bf16.f32 " \
        "{%0,%1,%2,%3}, {%4,%5,%6,%7}, {%8,%9}, {%0,%1,%2,%3};" \
        : "+f"((d)[0]), "+f"((d)[1]), "+f"((d)[2]), "+f"((d)[3]) \
        : "r"((a)[0]), "r"((a)[1]), "r"((a)[2]), "r"((a)[3]), "r"(b0), "r"(b1))

// ---------------------------------------------------------------------------
// W3 conversion: (E,512,512) fp32 -> g_B3[e][n][hi(512)|lo(512)] (transposed)
// ---------------------------------------------------------------------------
__global__ __launch_bounds__(256) void conv_w3(const float* __restrict__ W)
{
    __shared__ float sm[32][33];
    const int kt = blockIdx.x, nt = blockIdx.y, e = blockIdx.z;
    const int k0 = kt * 32, n0 = nt * 32;
    const int tid = threadIdx.x;
    #pragma unroll
    for (int i = 0; i < 4; i++) {
        int idx = tid + i * 256;
        int kk = idx >> 5, nn = idx & 31;
        sm[kk][nn] = W[((size_t)e * HH + k0 + kk) * HH + n0 + nn];
    }
    __syncthreads();
    const int n = tid >> 3, g = tid & 7;
    __nv_bfloat16 hi[4], lo[4];
    #pragma unroll
    for (int j = 0; j < 4; j++) {
        float x = sm[g * 4 + j][n];
        hi[j] = __float2bfloat16_rn(x);
        lo[j] = __float2bfloat16_rn(x - __bfloat162float(hi[j]));
    }
    __nv_bfloat16* dst = &g_B3[e][n0 + n][k0 + g * 4];
    *reinterpret_cast<uint2*>(dst)       = make_uint2(pk(hi[0], hi[1]), pk(hi[2], hi[3]));
    *reinterpret_cast<uint2*>(dst + 512) = make_uint2(pk(lo[0], lo[1]), pk(lo[2], lo[3]));
}

// ---------------------------------------------------------------------------
// Pairing + per-expert sample lists
// ---------------------------------------------------------------------------
__global__ void k_pairs(const int* __restrict__ cat_ids)
{
    int e = threadIdx.x;  // 32 threads
    int cnt = 0;
    for (int s = 0; s < BSZ; s++) cnt += (cat_ids[s] == e);
    g_scnt[e] = cnt;
    int np = (cnt + 1) >> 1;
    int inc = np;
    for (int d = 1; d < 32; d <<= 1) {
        int v = __shfl_up_sync(0xffffffffu, inc, d);
        if (e >= d) inc += v;
    }
    int off = inc - np;
    if (e == 31) g_npairs = off + np;
    int a = -1, w = off, li = 0;
    for (int s = 0; s < BSZ; s++) {
        if (cat_ids[s] == e) {
            g_slist[e][li++] = s;
            if (a < 0) a = s;
            else { g_pairs[w++] = make_int2(a, s); a = -1; }
        }
    }
    if (a >= 0) g_pairs[w++] = make_int2(a, a);
}

// ---------------------------------------------------------------------------
// kF: F[e] = W1[e] @ W2a[e]  (32x512 @ 512x512) fp32, plus c = b1@W2a + b2.
// grid (8 n-chunks of 64, EE) = 256 CTAs. W1[e]+b1[e] staged in dyn smem.
// Thread: one n column, 8 F-rows in registers -> 8 FMA per coalesced W2a load.
// ---------------------------------------------------------------------------
#define KF_SMEM ((AA * HH + HH) * 4)

__global__ __launch_bounds__(256) void kF(
    const float* __restrict__ W1, const float* __restrict__ W2,
    const float* __restrict__ b1, const float* __restrict__ b2)
{
    const int e = blockIdx.y;
    const int n0 = blockIdx.x * 64;
    const int tid = threadIdx.x;
    extern __shared__ float sm[];
    float* sW1 = sm;            // 32*512
    float* sb1 = sm + AA * HH;  // 512
    const float* W1e = W1 + (size_t)e * AA * HH;
    for (int i = tid; i < AA * HH / 4; i += 256)
        reinterpret_cast<float4*>(sW1)[i] = reinterpret_cast<const float4*>(W1e)[i];
    if (tid < 128)
        reinterpret_cast<float4*>(sb1)[tid] =
            reinterpret_cast<const float4*>(b1 + e * HH)[tid];
    __syncthreads();

    const int n = n0 + (tid & 63);
    const int abase = (tid >> 6) * 8;
    const float* W2a = W2 + (size_t)e * 1024 * HH + n;

    float acc[8] = {0,0,0,0,0,0,0,0};
    float accC = 0.f;
    #pragma unroll 4
    for (int h = 0; h < HH; h++) {
        float wv = W2a[(size_t)h * HH];
        #pragma unroll
        for (int i = 0; i < 8; i++) acc[i] += sW1[(abase + i) * HH + h] * wv;
        if (abase == 0) accC += sb1[h] * wv;
    }
    #pragma unroll
    for (int i = 0; i < 8; i++) g_F[e][abase + i][n] = acc[i];
    if (abase == 0) g_c[e][n] = accC + b2[e * HH + n];
}

// ---------------------------------------------------------------------------
// k_tauc: tc[s] = tau(t_s) @ W2tau[e]. grid (4 n-chunks of 128, EE).
// Loop-swapped: k outer (coalesced W2tau row load), sample group (4) inner in
// registers. tau computed in-CTA (no separate kernel / global round-trip).
// ---------------------------------------------------------------------------
__global__ __launch_bounds__(256) void k_tauc(
    const float* __restrict__ W2, const int* __restrict__ timesteps)
{
    const int e = blockIdx.y, n0 = blockIdx.x * 128, tid = threadIdx.x;
    const int cnt = g_scnt[e];
    if (cnt == 0) return;
    const int n = tid & 127, kh = tid >> 7;   // 2 k-halves
    __shared__ float stau[4][512];
    __shared__ float sred[2][4][128];
    const float C = 9.210340371976184f / 256.0f;
    const float* W2t = W2 + ((size_t)e * 1024 + 512) * HH + n0 + n;

    for (int g0 = 0; g0 < cnt; g0 += 4) {
        const int gc = min(4, cnt - g0);
        for (int g = 0; g < gc; g++) {
            int s = g_slist[e][g0 + g];
            float tval = (float)timesteps[s];
            for (int kk = tid; kk < 512; kk += 256) {
                int j = kk & 255;
                float f = tval * expf(-(float)j * C);
                stau[g][kk] = (kk < 256) ? sinf(f) : cosf(f);
            }
        }
        __syncthreads();
        float acc[4] = {0,0,0,0};
        #pragma unroll 4
        for (int k = kh * 256; k < kh * 256 + 256; k++) {
            float wv = W2t[(size_t)k * HH];
            #pragma unroll
            for (int g = 0; g < 4; g++) acc[g] += stau[g][k] * wv;
        }
        #pragma unroll
        for (int g = 0; g < 4; g++) sred[kh][g][n] = acc[g];
        __syncthreads();
        if (kh == 0)
            for (int g = 0; g < gc; g++) {
                int s = g_slist[e][g0 + g];
                g_tc[s][n0 + n] = sred[0][g][n] + sred[1][g][n];
            }
        __syncthreads();
    }
}

// ---------------------------------------------------------------------------
// k2: y2 = actions@F[e] (K=32) + tc + c; x2 = swish(y2) -> hi/lo bf16 in g_A3
// ---------------------------------------------------------------------------
__global__ __launch_bounds__(256) void k2_mid(
    const float* __restrict__ actions, const int* __restrict__ cat_ids)
{
    const int s = blockIdx.x, tid = threadIdx.x;
    const int tbase = blockIdx.y * 32;
    const int e = cat_ids[s];
    __shared__ float sA[32][36];

    const float* Ab = actions + ((size_t)s * TT + tbase) * AA;
    {
        int row = tid >> 3, c4 = tid & 7;
        float4 v = *reinterpret_cast<const float4*>(&Ab[row * AA + c4 * 4]);
        *reinterpret_cast<float4*>(&sA[row][c4 * 4]) = v;
    }
    __syncthreads();

    const int h0 = 2 * tid;
    float2 w[AA];
    #pragma unroll
    for (int k = 0; k < AA; k++)
        w[k] = *reinterpret_cast<const float2*>(&g_F[e][k][h0]);
    float2 tc = *reinterpret_cast<const float2*>(&g_tc[s][h0]);
    float2 cc = *reinterpret_cast<const float2*>(&g_c[e][h0]);
    const float base0 = tc.x + cc.x, base1 = tc.y + cc.y;

    for (int tl = 0; tl < 32; tl++) {
        float a0 = base0, a1 = base1;
        #pragma unroll
        for (int k = 0; k < AA; k++) {
            float av = sA[tl][k];
            a0 += av * w[k].x; a1 += av * w[k].y;
        }
        a0 = a0 * (1.f / (1.f + expf(-a0)));
        a1 = a1 * (1.f / (1.f + expf(-a1)));
        __nv_bfloat16 hh0 = __float2bfloat16_rn(a0), hh1 = __float2bfloat16_rn(a1);
        __nv_bfloat16 ll0 = __float2bfloat16_rn(a0 - __bfloat162float(hh0));
        __nv_bfloat16 ll1 = __float2bfloat16_rn(a1 - __bfloat162float(hh1));
        __nv_bfloat16* row = &g_A3[s][tbase + tl][0];
        *reinterpret_cast<unsigned*>(row + h0)       = pk(hh0, hh1);
        *reinterpret_cast<unsigned*>(row + 512 + h0) = pk(ll0, ll1);
    }
}

// ---------------------------------------------------------------------------
// Layer-3 GEMM (mma.sync, fused 3-term hi/lo). M=128 (sample pair), N=256.
// ---------------------------------------------------------------------------
#define STAGE_BYTES 98304
#define GSMEM (2 * STAGE_BYTES + 1024)

__global__ __launch_bounds__(256, 1) void gemm3(
    const float* __restrict__ bias, const int* __restrict__ cat_ids,
    float* __restrict__ out)
{
    constexpr int KP  = 512;
    constexpr int TPC = KP / 64;

    const int mt_blk = blockIdx.y;
    if (mt_blk >= g_npairs) return;
    const int n0 = blockIdx.x * 256;
    const int2 pr = g_pairs[mt_blk];
    const int s0 = pr.x, s1 = pr.y;
    const int e  = cat_ids[s0];

    extern __shared__ char smem[];
    const uint32_t sb = (smem_u32(smem) + 127) & ~127u;

    const int tid  = threadIdx.x;
    const int wid  = tid >> 5;
    const int lane = tid & 31;
    const int mWarp = (wid >> 2) * 64;
    const int nWarp = (wid & 3) * 64;

    const __nv_bfloat16* aRow[4]; uint32_t dAo[4];
    #pragma unroll
    for (int i = 0; i < 4; i++) {
        int idx = tid + 256 * i;
        int r = idx >> 3, sg = idx & 7;
        int samp = (r < 64) ? s0 : s1;
        aRow[i] = &g_A3[samp][r & 63][0] + sg * 8;
        dAo[i]  = (uint32_t)(r * 128 + ((sg * 16) ^ ((r & 7) * 16)));
    }
    const __nv_bfloat16* bRow[8]; uint32_t dBo[8];
    #pragma unroll
    for (int i = 0; i < 8; i++) {
        int idx = tid + 256 * i;
        int r = idx >> 3, sg = idx & 7;
        bRow[i] = &g_B3[e][n0 + r][0] + sg * 8;
        dBo[i]  = (uint32_t)(r * 128 + ((sg * 16) ^ ((r & 7) * 16)));
    }

    auto issue = [&](int c) {
        int pkk = c * 64;
        uint32_t sof = sb + (uint32_t)(c & 1) * STAGE_BYTES;
        #pragma unroll
        for (int i = 0; i < 4; i++) {
            CP_ASYNC16(sof + dAo[i],         aRow[i] + pkk);
            CP_ASYNC16(sof + 16384 + dAo[i], aRow[i] + KP + pkk);
        }
        #pragma unroll
        for (int i = 0; i < 8; i++) {
            CP_ASYNC16(sof + 32768 + dBo[i], bRow[i] + pkk);
            CP_ASYNC16(sof + 65536 + dBo[i], bRow[i] + KP + pkk);
        }
        CP_COMMIT();
    };

    const uint32_t maskk = (lane & 7) * 16;
    const uint32_t aRowB = (uint32_t)(mWarp + (lane & 7) + ((lane & 8) ? 8 : 0)) * 128;
    const uint32_t kextA = (lane & 16) ? 16 : 0;
    const uint32_t bRowB = (uint32_t)((nWarp + (lane & 7) + ((lane & 16) ? 8 : 0)) * 128);
    const uint32_t kextB = (lane & 8) ? 16 : 0;

    float acc[4][8][4];
    #pragma unroll
    for (int m = 0; m < 4; m++)
        #pragma unroll
        for (int j = 0; j < 8; j++)
            #pragma unroll
            for (int q = 0; q < 4; q++) acc[m][j][q] = 0.f;

    issue(0);

    for (int c = 0; c < TPC; c++) {
        __syncthreads();
        if (c + 1 < TPC) { issue(c + 1); CP_WAIT1(); } else { CP_WAIT0(); }
        __syncthreads();

        const uint32_t stb = sb + (uint32_t)(c & 1) * STAGE_BYTES;
        #pragma unroll
        for (int ks = 0; ks < 4; ks++) {
            const uint32_t kA = (uint32_t)(ks * 32 + kextA) ^ maskk;
            const uint32_t kB = (uint32_t)(ks * 32 + kextB) ^ maskk;
            uint32_t a[4][4], b[4][4], c2[4][4];
            #pragma unroll
            for (int m = 0; m < 4; m++)
                LDSM_X4(a[m], stb + aRowB + m * 2048 + kA);
            #pragma unroll
            for (int nt = 0; nt < 4; nt++)
                LDSM_X4(b[nt], stb + 32768 + bRowB + nt * 2048 + kB);
            #pragma unroll
            for (int m = 0; m < 4; m++)
                #pragma unroll
                for (int j = 0; j < 8; j++)
                    MMA16816(acc[m][j], a[m], b[j >> 1][(j & 1) * 2], b[j >> 1][(j & 1) * 2 + 1]);
            #pragma unroll
            for (int m = 0; m < 4; m++)
                LDSM_X4(c2[m], stb + 16384 + aRowB + m * 2048 + kA);
            #pragma unroll
            for (int m = 0; m < 4; m++)
                #pragma unroll
                for (int j = 0; j < 8; j++)
                    MMA16816(acc[m][j], c2[m], b[j >> 1][(j & 1) * 2], b[j >> 1][(j & 1) * 2 + 1]);
            #pragma unroll
            for (int nt = 0; nt < 4; nt++)
                LDSM_X4(c2[nt], stb + 65536 + bRowB + nt * 2048 + kB);
            #pragma unroll
            for (int m = 0; m < 4; m++)
                #pragma unroll
                for (int j = 0; j < 8; j++)
                    MMA16816(acc[m][j], a[m], c2[j >> 1][(j & 1) * 2], c2[j >> 1][(j & 1) * 2 + 1]);
        }
    }

    const float* biasE = bias + e * HH;
    const int sampW = (mWarp < 64) ? s0 : s1;
    #pragma unroll
    for (int m = 0; m < 4; m++) {
        int rloc = mWarp + m * 16 + (lane >> 2);
        int t0 = rloc & 63, t1 = (rloc + 8) & 63;
        #pragma unroll
        for (int j = 0; j < 8; j++) {
            int cidx = n0 + nWarp + j * 8 + (lane & 3) * 2;
            float2 bv = *reinterpret_cast<const float2*>(&biasE[cidx]);
            float* p0 = out + ((size_t)sampW * TT + t0) * HH + cidx;
            float* p1 = out + ((size_t)sampW * TT + t1) * HH + cidx;
            *reinterpret_cast<float2*>(p0) = make_float2(acc[m][j][0] + bv.x, acc[m][j][1] + bv.y);
            *reinterpret_cast<float2*>(p1) = make_float2(acc[m][j][2] + bv.x, acc[m][j][3] + bv.y);
        }
    }
}

// ---------------------------------------------------------------------------
extern "C" void kernel_launch(void* const* d_in, const int* in_sizes, int n_in,
                              void* d_out, int out_size)
{
    const float* actions   = (const float*)d_in[0];
    const int*   timesteps = (const int*)  d_in[1];
    const int*   cat_ids   = (const int*)  d_in[2];
    const float* W1        = (const float*)d_in[3];
    const float* b1        = (const float*)d_in[4];
    const float* W2        = (const float*)d_in[5];
    const float* b2        = (const float*)d_in[6];
    const float* W3        = (const float*)d_in[7];
    const float* b3        = (const float*)d_in[8];
    float* out = (float*)d_out;

    cudaFuncSetAttribute(gemm3, cudaFuncAttributeMaxDynamicSharedMemorySize, GSMEM);
    cudaFuncSetAttribute(kF, cudaFuncAttributeMaxDynamicSharedMemorySize, KF_SMEM);

    conv_w3<<<dim3(16, 16, EE), 256>>>(W3);
    k_pairs<<<1, 32>>>(cat_ids);
    kF<<<dim3(8, EE), 256, KF_SMEM>>>(W1, W2, b1, b2);
    k_tauc<<<dim3(4, EE), 256>>>(W2, timesteps);
    k2_mid<<<dim3(BSZ, 2), 256>>>(actions, cat_ids);
    gemm3<<<dim3(2, 144), 256, GSMEM>>>(b3, cat_ids, out);
}

// round 14
// speedup vs baseline: 2.0985x; 1.4863x over previous
#include <cuda_runtime.h>
#include <cuda_bf16.h>
#include <cstdint>
#include <math.h>

#define BSZ 256
#define TT  64
#define AA  32
#define HH  512
#define EE  32

// -------- device scratch (allocation-free) --------
__device__ __align__(256) __nv_bfloat16 g_B3[EE][HH][1024]; // [e][n][hi(512)|lo(512)]
__device__ __align__(256) __nv_bfloat16 g_A3[BSZ][TT][1024]; // x2 [hi(512)|lo(512)]
__device__ __align__(256) float g_F[EE][AA][HH];    // fused W1@W2a
__device__ __align__(256) float g_c[EE][HH];        // b1@W2a + b2
__device__ __align__(256) float g_tc[BSZ][HH];      // tau @ W2tau
__device__ __align__(256) float g_Fp[4][EE][AA][HH];  // h-chunk partials
__device__ __align__(256) float g_cp[4][EE][HH];
__device__ __align__(256) float g_tcp[4][BSZ][HH];    // k-chunk partials
__device__ int2 g_pairs[160];
__device__ int  g_npairs;
__device__ int  g_scnt[EE];
__device__ int  g_slist[EE][BSZ];

// -------- helpers --------
__device__ __forceinline__ uint32_t smem_u32(const void* p){
    uint32_t a;
    asm("{ .reg .u64 t; cvta.to.shared.u64 t, %1; cvt.u32.u64 %0, t; }" : "=r"(a) : "l"(p));
    return a;
}
__device__ __forceinline__ unsigned pk(__nv_bfloat16 a, __nv_bfloat16 b){
    unsigned short x = *reinterpret_cast<unsigned short*>(&a);
    unsigned short y = *reinterpret_cast<unsigned short*>(&b);
    return (unsigned)x | ((unsigned)y << 16);
}

#define CP_ASYNC16(dst, src) \
    asm volatile("cp.async.cg.shared.global [%0], [%1], 16;" :: "r"(dst), "l"(src))
#define CP_COMMIT() asm volatile("cp.async.commit_group;" ::: "memory")
#define CP_WAIT0()  asm volatile("cp.async.wait_group 0;" ::: "memory")
#define CP_WAIT1()  asm volatile("cp.async.wait_group 1;" ::: "memory")

#define LDSM_X4(r, addr) \
    asm volatile("ldmatrix.sync.aligned.m8n8.x4.shared.b16 {%0,%1,%2,%3}, [%4];" \
        : "=r"((r)[0]), "=r"((r)[1]), "=r"((r)[2]), "=r"((r)[3]) : "r"(addr))

#define MMA16816(d, a, b0, b1) \
    asm volatile("mma.sync.aligned.m16n8k16.row.col.f32.bf16.bf16.f32 " \
        "{%0,%1,%2,%3}, {%4,%5,%6,%7}, {%8,%9}, {%0,%1,%2,%3};" \
        : "+f"((d)[0]), "+f"((d)[1]), "+f"((d)[2]), "+f"((d)[3]) \
        : "r"((a)[0]), "r"((a)[1]), "r"((a)[2]), "r"((a)[3]), "r"(b0), "r"(b1))

// ---------------------------------------------------------------------------
// W3 conversion: (E,512,512) fp32 -> g_B3[e][n][hi(512)|lo(512)] (transposed)
// ---------------------------------------------------------------------------
__global__ __launch_bounds__(256) void conv_w3(const float* __restrict__ W)
{
    __shared__ float sm[32][33];
    const int kt = blockIdx.x, nt = blockIdx.y, e = blockIdx.z;
    const int k0 = kt * 32, n0 = nt * 32;
    const int tid = threadIdx.x;
    #pragma unroll
    for (int i = 0; i < 4; i++) {
        int idx = tid + i * 256;
        int kk = idx >> 5, nn = idx & 31;
        sm[kk][nn] = W[((size_t)e * HH + k0 + kk) * HH + n0 + nn];
    }
    __syncthreads();
    const int n = tid >> 3, g = tid & 7;
    __nv_bfloat16 hi[4], lo[4];
    #pragma unroll
    for (int j = 0; j < 4; j++) {
        float x = sm[g * 4 + j][n];
        hi[j] = __float2bfloat16_rn(x);
        lo[j] = __float2bfloat16_rn(x - __bfloat162float(hi[j]));
    }
    __nv_bfloat16* dst = &g_B3[e][n0 + n][k0 + g * 4];
    *reinterpret_cast<uint2*>(dst)       = make_uint2(pk(hi[0], hi[1]), pk(hi[2], hi[3]));
    *reinterpret_cast<uint2*>(dst + 512) = make_uint2(pk(lo[0], lo[1]), pk(lo[2], lo[3]));
}

// ---------------------------------------------------------------------------
// Pairing + per-expert sample lists
// ---------------------------------------------------------------------------
__global__ void k_pairs(const int* __restrict__ cat_ids)
{
    int e = threadIdx.x;  // 32 threads
    int cnt = 0;
    for (int s = 0; s < BSZ; s++) cnt += (cat_ids[s] == e);
    g_scnt[e] = cnt;
    int np = (cnt + 1) >> 1;
    int inc = np;
    for (int d = 1; d < 32; d <<= 1) {
        int v = __shfl_up_sync(0xffffffffu, inc, d);
        if (e >= d) inc += v;
    }
    int off = inc - np;
    if (e == 31) g_npairs = off + np;
    int a = -1, w = off, li = 0;
    for (int s = 0; s < BSZ; s++) {
        if (cat_ids[s] == e) {
            g_slist[e][li++] = s;
            if (a < 0) a = s;
            else { g_pairs[w++] = make_int2(a, s); a = -1; }
        }
    }
    if (a >= 0) g_pairs[w++] = make_int2(a, a);
}

// ---------------------------------------------------------------------------
// kF_part: partial F = W1[:, hc*128:+128] @ W2a[hc*128:+128, n-chunk].
// grid (8 n-chunks of 64, EE, 4 h-chunks) = 1024 CTAs. unroll 8 -> high MLP.
// ---------------------------------------------------------------------------
__global__ __launch_bounds__(256) void kF_part(
    const float* __restrict__ W1, const float* __restrict__ W2,
    const float* __restrict__ b1)
{
    const int e = blockIdx.y, hc = blockIdx.z;
    const int n0 = blockIdx.x * 64;
    const int tid = threadIdx.x;
    __shared__ float sW1[AA * 128];   // W1 slab [32][128]
    __shared__ float sb1[128];
    const float* W1e = W1 + (size_t)e * AA * HH + hc * 128;
    for (int i = tid; i < AA * 128 / 4; i += 256) {
        int a = i / 32, q = i % 32;   // 32 float4 per row
        reinterpret_cast<float4*>(sW1)[a * 32 + q] =
            *reinterpret_cast<const float4*>(&W1e[a * HH + q * 4]);
    }
    if (tid < 32)
        reinterpret_cast<float4*>(sb1)[tid] =
            *reinterpret_cast<const float4*>(&b1[e * HH + hc * 128 + tid * 4]);
    __syncthreads();

    const int n = n0 + (tid & 63);
    const int abase = (tid >> 6) * 8;
    const float* W2a = W2 + ((size_t)e * 1024 + hc * 128) * HH + n;

    float acc[8] = {0,0,0,0,0,0,0,0};
    float accC = 0.f;
    #pragma unroll 8
    for (int h = 0; h < 128; h++) {
        float wv = W2a[(size_t)h * HH];
        #pragma unroll
        for (int i = 0; i < 8; i++) acc[i] += sW1[(abase + i) * 128 + h] * wv;
        if (abase == 0) accC += sb1[h] * wv;
    }
    #pragma unroll
    for (int i = 0; i < 8; i++) g_Fp[hc][e][abase + i][n] = acc[i];
    if (abase == 0) g_cp[hc][e][n] = accC;
}

// ---------------------------------------------------------------------------
// k_tauc_part: partial tc over k-chunk of 128. grid (4 n-chunks, EE, 4 k).
// tau slab computed in-CTA; sample groups of 4; unroll 8.
// ---------------------------------------------------------------------------
__global__ __launch_bounds__(256) void k_tauc_part(
    const float* __restrict__ W2, const int* __restrict__ timesteps)
{
    const int e = blockIdx.y, kc = blockIdx.z;
    const int n0 = blockIdx.x * 128, tid = threadIdx.x;
    const int cnt = g_scnt[e];
    if (cnt == 0) return;
    const int n = tid & 127, kh = tid >> 7;   // 2 k-sub-halves of 64
    __shared__ float stau[4][128];
    __shared__ float sred[2][4][128];
    const float C = 9.210340371976184f / 256.0f;
    const float* W2t = W2 + ((size_t)e * 1024 + 512 + kc * 128) * HH + n0 + n;

    for (int g0 = 0; g0 < cnt; g0 += 4) {
        const int gc = min(4, cnt - g0);
        for (int idx = tid; idx < gc * 128; idx += 256) {
            int g = idx >> 7, kk = idx & 127;
            int s = g_slist[e][g0 + g];
            float tval = (float)timesteps[s];
            int kidx = kc * 128 + kk;
            int j = kidx & 255;
            float f = tval * expf(-(float)j * C);
            stau[g][kk] = (kidx < 256) ? sinf(f) : cosf(f);
        }
        __syncthreads();
        float acc[4] = {0,0,0,0};
        #pragma unroll 8
        for (int k = kh * 64; k < kh * 64 + 64; k++) {
            float wv = W2t[(size_t)k * HH];
            #pragma unroll
            for (int g = 0; g < 4; g++) acc[g] += stau[g][k] * wv;
        }
        #pragma unroll
        for (int g = 0; g < 4; g++) sred[kh][g][n] = acc[g];
        __syncthreads();
        if (kh == 0)
            for (int g = 0; g < gc; g++) {
                int s = g_slist[e][g0 + g];
                g_tcp[kc][s][n0 + n] = sred[0][g][n] + sred[1][g][n];
            }
        __syncthreads();
    }
}

// ---------------------------------------------------------------------------
// kRed: sum the 4 partials -> g_F, g_c (+b2), g_tc. float4 granularity.
// F: 131072 f4, c: 4096 f4, tc: 32768 f4 -> 167936 f4 = 656 CTAs x 256.
// ---------------------------------------------------------------------------
#define F4COUNT  131072
#define C4COUNT  4096
#define TC4COUNT 32768

__global__ __launch_bounds__(256) void kRed(const float* __restrict__ b2)
{
    const int idx = blockIdx.x * 256 + threadIdx.x;
    if (idx < F4COUNT) {
        const float4* p = reinterpret_cast<const float4*>(&g_Fp[0][0][0][0]);
        float4 a = p[idx], b = p[idx + F4COUNT], c = p[idx + 2 * F4COUNT], d = p[idx + 3 * F4COUNT];
        reinterpret_cast<float4*>(&g_F[0][0][0])[idx] =
            make_float4(a.x + b.x + c.x + d.x, a.y + b.y + c.y + d.y,
                        a.z + b.z + c.z + d.z, a.w + b.w + c.w + d.w);
    } else if (idx < F4COUNT + C4COUNT) {
        const int i = idx - F4COUNT;
        const float4* p = reinterpret_cast<const float4*>(&g_cp[0][0][0]);
        float4 a = p[i], b = p[i + C4COUNT], c = p[i + 2 * C4COUNT], d = p[i + 3 * C4COUNT];
        float4 bb = reinterpret_cast<const float4*>(b2)[i];
        reinterpret_cast<float4*>(&g_c[0][0])[i] =
            make_float4(a.x + b.x + c.x + d.x + bb.x, a.y + b.y + c.y + d.y + bb.y,
                        a.z + b.z + c.z + d.z + bb.z, a.w + b.w + c.w + d.w + bb.w);
    } else {
        const int i = idx - F4COUNT - C4COUNT;
        if (i < TC4COUNT) {
            const float4* p = reinterpret_cast<const float4*>(&g_tcp[0][0][0]);
            float4 a = p[i], b = p[i + TC4COUNT], c = p[i + 2 * TC4COUNT], d = p[i + 3 * TC4COUNT];
            reinterpret_cast<float4*>(&g_tc[0][0])[i] =
                make_float4(a.x + b.x + c.x + d.x, a.y + b.y + c.y + d.y,
                            a.z + b.z + c.z + d.z, a.w + b.w + c.w + d.w);
        }
    }
}

// ---------------------------------------------------------------------------
// k2: y2 = actions@F[e] (K=32) + tc + c; x2 = swish(y2) -> hi/lo bf16 in g_A3
// ---------------------------------------------------------------------------
__global__ __launch_bounds__(256) void k2_mid(
    const float* __restrict__ actions, const int* __restrict__ cat_ids)
{
    const int s = blockIdx.x, tid = threadIdx.x;
    const int tbase = blockIdx.y * 32;
    const int e = cat_ids[s];
    __shared__ float sA[32][36];

    const float* Ab = actions + ((size_t)s * TT + tbase) * AA;
    {
        int row = tid >> 3, c4 = tid & 7;
        float4 v = *reinterpret_cast<const float4*>(&Ab[row * AA + c4 * 4]);
        *reinterpret_cast<float4*>(&sA[row][c4 * 4]) = v;
    }
    __syncthreads();

    const int h0 = 2 * tid;
    float2 w[AA];
    #pragma unroll
    for (int k = 0; k < AA; k++)
        w[k] = *reinterpret_cast<const float2*>(&g_F[e][k][h0]);
    float2 tc = *reinterpret_cast<const float2*>(&g_tc[s][h0]);
    float2 cc = *reinterpret_cast<const float2*>(&g_c[e][h0]);
    const float base0 = tc.x + cc.x, base1 = tc.y + cc.y;

    for (int tl = 0; tl < 32; tl++) {
        float a0 = base0, a1 = base1;
        #pragma unroll
        for (int k = 0; k < AA; k++) {
            float av = sA[tl][k];
            a0 += av * w[k].x; a1 += av * w[k].y;
        }
        a0 = a0 * (1.f / (1.f + expf(-a0)));
        a1 = a1 * (1.f / (1.f + expf(-a1)));
        __nv_bfloat16 hh0 = __float2bfloat16_rn(a0), hh1 = __float2bfloat16_rn(a1);
        __nv_bfloat16 ll0 = __float2bfloat16_rn(a0 - __bfloat162float(hh0));
        __nv_bfloat16 ll1 = __float2bfloat16_rn(a1 - __bfloat162float(hh1));
        __nv_bfloat16* row = &g_A3[s][tbase + tl][0];
        *reinterpret_cast<unsigned*>(row + h0)       = pk(hh0, hh1);
        *reinterpret_cast<unsigned*>(row + 512 + h0) = pk(ll0, ll1);
    }
}

// ---------------------------------------------------------------------------
// Layer-3 GEMM (mma.sync, fused 3-term hi/lo). M=128 (sample pair), N=256.
// ---------------------------------------------------------------------------
#define STAGE_BYTES 98304
#define GSMEM (2 * STAGE_BYTES + 1024)

__global__ __launch_bounds__(256, 1) void gemm3(
    const float* __restrict__ bias, const int* __restrict__ cat_ids,
    float* __restrict__ out)
{
    constexpr int KP  = 512;
    constexpr int TPC = KP / 64;

    const int mt_blk = blockIdx.y;
    if (mt_blk >= g_npairs) return;
    const int n0 = blockIdx.x * 256;
    const int2 pr = g_pairs[mt_blk];
    const int s0 = pr.x, s1 = pr.y;
    const int e  = cat_ids[s0];

    extern __shared__ char smem[];
    const uint32_t sb = (smem_u32(smem) + 127) & ~127u;

    const int tid  = threadIdx.x;
    const int wid  = tid >> 5;
    const int lane = tid & 31;
    const int mWarp = (wid >> 2) * 64;
    const int nWarp = (wid & 3) * 64;

    const __nv_bfloat16* aRow[4]; uint32_t dAo[4];
    #pragma unroll
    for (int i = 0; i < 4; i++) {
        int idx = tid + 256 * i;
        int r = idx >> 3, sg = idx & 7;
        int samp = (r < 64) ? s0 : s1;
        aRow[i] = &g_A3[samp][r & 63][0] + sg * 8;
        dAo[i]  = (uint32_t)(r * 128 + ((sg * 16) ^ ((r & 7) * 16)));
    }
    const __nv_bfloat16* bRow[8]; uint32_t dBo[8];
    #pragma unroll
    for (int i = 0; i < 8; i++) {
        int idx = tid + 256 * i;
        int r = idx >> 3, sg = idx & 7;
        bRow[i] = &g_B3[e][n0 + r][0] + sg * 8;
        dBo[i]  = (uint32_t)(r * 128 + ((sg * 16) ^ ((r & 7) * 16)));
    }

    auto issue = [&](int c) {
        int pkk = c * 64;
        uint32_t sof = sb + (uint32_t)(c & 1) * STAGE_BYTES;
        #pragma unroll
        for (int i = 0; i < 4; i++) {
            CP_ASYNC16(sof + dAo[i],         aRow[i] + pkk);
            CP_ASYNC16(sof + 16384 + dAo[i], aRow[i] + KP + pkk);
        }
        #pragma unroll
        for (int i = 0; i < 8; i++) {
            CP_ASYNC16(sof + 32768 + dBo[i], bRow[i] + pkk);
            CP_ASYNC16(sof + 65536 + dBo[i], bRow[i] + KP + pkk);
        }
        CP_COMMIT();
    };

    const uint32_t maskk = (lane & 7) * 16;
    const uint32_t aRowB = (uint32_t)(mWarp + (lane & 7) + ((lane & 8) ? 8 : 0)) * 128;
    const uint32_t kextA = (lane & 16) ? 16 : 0;
    const uint32_t bRowB = (uint32_t)((nWarp + (lane & 7) + ((lane & 16) ? 8 : 0)) * 128);
    const uint32_t kextB = (lane & 8) ? 16 : 0;

    float acc[4][8][4];
    #pragma unroll
    for (int m = 0; m < 4; m++)
        #pragma unroll
        for (int j = 0; j < 8; j++)
            #pragma unroll
            for (int q = 0; q < 4; q++) acc[m][j][q] = 0.f;

    issue(0);

    for (int c = 0; c < TPC; c++) {
        __syncthreads();
        if (c + 1 < TPC) { issue(c + 1); CP_WAIT1(); } else { CP_WAIT0(); }
        __syncthreads();

        const uint32_t stb = sb + (uint32_t)(c & 1) * STAGE_BYTES;
        #pragma unroll
        for (int ks = 0; ks < 4; ks++) {
            const uint32_t kA = (uint32_t)(ks * 32 + kextA) ^ maskk;
            const uint32_t kB = (uint32_t)(ks * 32 + kextB) ^ maskk;
            uint32_t a[4][4], b[4][4], c2[4][4];
            #pragma unroll
            for (int m = 0; m < 4; m++)
                LDSM_X4(a[m], stb + aRowB + m * 2048 + kA);
            #pragma unroll
            for (int nt = 0; nt < 4; nt++)
                LDSM_X4(b[nt], stb + 32768 + bRowB + nt * 2048 + kB);
            #pragma unroll
            for (int m = 0; m < 4; m++)
                #pragma unroll
                for (int j = 0; j < 8; j++)
                    MMA16816(acc[m][j], a[m], b[j >> 1][(j & 1) * 2], b[j >> 1][(j & 1) * 2 + 1]);
            #pragma unroll
            for (int m = 0; m < 4; m++)
                LDSM_X4(c2[m], stb + 16384 + aRowB + m * 2048 + kA);
            #pragma unroll
            for (int m = 0; m < 4; m++)
                #pragma unroll
                for (int j = 0; j < 8; j++)
                    MMA16816(acc[m][j], c2[m], b[j >> 1][(j & 1) * 2], b[j >> 1][(j & 1) * 2 + 1]);
            #pragma unroll
            for (int nt = 0; nt < 4; nt++)
                LDSM_X4(c2[nt], stb + 65536 + bRowB + nt * 2048 + kB);
            #pragma unroll
            for (int m = 0; m < 4; m++)
                #pragma unroll
                for (int j = 0; j < 8; j++)
                    MMA16816(acc[m][j], a[m], c2[j >> 1][(j & 1) * 2], c2[j >> 1][(j & 1) * 2 + 1]);
        }
    }

    const float* biasE = bias + e * HH;
    const int sampW = (mWarp < 64) ? s0 : s1;
    #pragma unroll
    for (int m = 0; m < 4; m++) {
        int rloc = mWarp + m * 16 + (lane >> 2);
        int t0 = rloc & 63, t1 = (rloc + 8) & 63;
        #pragma unroll
        for (int j = 0; j < 8; j++) {
            int cidx = n0 + nWarp + j * 8 + (lane & 3) * 2;
            float2 bv = *reinterpret_cast<const float2*>(&biasE[cidx]);
            float* p0 = out + ((size_t)sampW * TT + t0) * HH + cidx;
            float* p1 = out + ((size_t)sampW * TT + t1) * HH + cidx;
            *reinterpret_cast<float2*>(p0) = make_float2(acc[m][j][0] + bv.x, acc[m][j][1] + bv.y);
            *reinterpret_cast<float2*>(p1) = make_float2(acc[m][j][2] + bv.x, acc[m][j][3] + bv.y);
        }
    }
}

// ---------------------------------------------------------------------------
extern "C" void kernel_launch(void* const* d_in, const int* in_sizes, int n_in,
                              void* d_out, int out_size)
{
    const float* actions   = (const float*)d_in[0];
    const int*   timesteps = (const int*)  d_in[1];
    const int*   cat_ids   = (const int*)  d_in[2];
    const float* W1        = (const float*)d_in[3];
    const float* b1        = (const float*)d_in[4];
    const float* W2        = (const float*)d_in[5];
    const float* b2        = (const float*)d_in[6];
    const float* W3        = (const float*)d_in[7];
    const float* b3        = (const float*)d_in[8];
    float* out = (float*)d_out;

    cudaFuncSetAttribute(gemm3, cudaFuncAttributeMaxDynamicSharedMemorySize, GSMEM);

    conv_w3<<<dim3(16, 16, EE), 256>>>(W3);
    k_pairs<<<1, 32>>>(cat_ids);
    kF_part<<<dim3(8, EE, 4), 256>>>(W1, W2, b1);
    k_tauc_part<<<dim3(4, EE, 4), 256>>>(W2, timesteps);
    kRed<<<656, 256>>>(b2);
    k2_mid<<<dim3(BSZ, 2), 256>>>(actions, cat_ids);
    gemm3<<<dim3(2, 144), 256, GSMEM>>>(b3, cat_ids, out);
}

// round 15
// speedup vs baseline: 2.1247x; 1.0125x over previous
#include <cuda_runtime.h>
#include <cuda_bf16.h>
#include <cstdint>
#include <math.h>

#define BSZ 256
#define TT  64
#define AA  32
#define HH  512
#define EE  32

// -------- device scratch (allocation-free) --------
__device__ __align__(256) __nv_bfloat16 g_B3[EE][HH][1024]; // [e][n][hi(512)|lo(512)]
__device__ __align__(256) __nv_bfloat16 g_A3[BSZ][TT][1024]; // x2 [hi(512)|lo(512)]
__device__ __align__(256) float g_F[EE][AA][HH];    // fused W1@W2a
__device__ __align__(256) float g_c[EE][HH];        // b1@W2a + b2
__device__ __align__(256) float g_tc[BSZ][HH];      // tau @ W2tau
__device__ __align__(256) float g_Fp[4][EE][AA][HH];  // h-chunk partials
__device__ __align__(256) float g_cp[4][EE][HH];
__device__ __align__(256) float g_tcp[4][BSZ][HH];    // k-chunk partials
__device__ int2 g_pairs[160];
__device__ int  g_npairs;
__device__ int  g_scnt[EE];
__device__ int  g_slist[EE][BSZ];

// -------- helpers --------
__device__ __forceinline__ uint32_t smem_u32(const void* p){
    uint32_t a;
    asm("{ .reg .u64 t; cvta.to.shared.u64 t, %1; cvt.u32.u64 %0, t; }" : "=r"(a) : "l"(p));
    return a;
}
__device__ __forceinline__ unsigned pk(__nv_bfloat16 a, __nv_bfloat16 b){
    unsigned short x = *reinterpret_cast<unsigned short*>(&a);
    unsigned short y = *reinterpret_cast<unsigned short*>(&b);
    return (unsigned)x | ((unsigned)y << 16);
}

#define CP_ASYNC16(dst, src) \
    asm volatile("cp.async.cg.shared.global [%0], [%1], 16;" :: "r"(dst), "l"(src))
#define CP_COMMIT() asm volatile("cp.async.commit_group;" ::: "memory")
#define CP_WAIT0()  asm volatile("cp.async.wait_group 0;" ::: "memory")
#define CP_WAIT1()  asm volatile("cp.async.wait_group 1;" ::: "memory")

#define LDSM_X4(r, addr) \
    asm volatile("ldmatrix.sync.aligned.m8n8.x4.shared.b16 {%0,%1,%2,%3}, [%4];" \
        : "=r"((r)[0]), "=r"((r)[1]), "=r"((r)[2]), "=r"((r)[3]) : "r"(addr))

#define MMA16816(d, a, b0, b1) \
    asm volatile("mma.sync.aligned.m16n8k16.row.col.f32.bf16.bf16.f32 " \
        "{%0,%1,%2,%3}, {%4,%5,%6,%7}, {%8,%9}, {%0,%1,%2,%3};" \
        : "+f"((d)[0]), "+f"((d)[1]), "+f"((d)[2]), "+f"((d)[3]) \
        : "r"((a)[0]), "r"((a)[1]), "r"((a)[2]), "r"((a)[3]), "r"(b0), "r"(b1))

// ---------------------------------------------------------------------------
// W3 conversion: (E,512,512) fp32 -> g_B3[e][n][hi(512)|lo(512)] (transposed)
// ---------------------------------------------------------------------------
__global__ __launch_bounds__(256) void conv_w3(const float* __restrict__ W)
{
    __shared__ float sm[32][33];
    const int kt = blockIdx.x, nt = blockIdx.y, e = blockIdx.z;
    const int k0 = kt * 32, n0 = nt * 32;
    const int tid = threadIdx.x;
    #pragma unroll
    for (int i = 0; i < 4; i++) {
        int idx = tid + i * 256;
        int kk = idx >> 5, nn = idx & 31;
        sm[kk][nn] = W[((size_t)e * HH + k0 + kk) * HH + n0 + nn];
    }
    __syncthreads();
    const int n = tid >> 3, g = tid & 7;
    __nv_bfloat16 hi[4], lo[4];
    #pragma unroll
    for (int j = 0; j < 4; j++) {
        float x = sm[g * 4 + j][n];
        hi[j] = __float2bfloat16_rn(x);
        lo[j] = __float2bfloat16_rn(x - __bfloat162float(hi[j]));
    }
    __nv_bfloat16* dst = &g_B3[e][n0 + n][k0 + g * 4];
    *reinterpret_cast<uint2*>(dst)       = make_uint2(pk(hi[0], hi[1]), pk(hi[2], hi[3]));
    *reinterpret_cast<uint2*>(dst + 512) = make_uint2(pk(lo[0], lo[1]), pk(lo[2], lo[3]));
}

// ---------------------------------------------------------------------------
// Pairing + per-expert sample lists
// ---------------------------------------------------------------------------
__global__ void k_pairs(const int* __restrict__ cat_ids)
{
    int e = threadIdx.x;  // 32 threads
    int cnt = 0;
    for (int s = 0; s < BSZ; s++) cnt += (cat_ids[s] == e);
    g_scnt[e] = cnt;
    int np = (cnt + 1) >> 1;
    int inc = np;
    for (int d = 1; d < 32; d <<= 1) {
        int v = __shfl_up_sync(0xffffffffu, inc, d);
        if (e >= d) inc += v;
    }
    int off = inc - np;
    if (e == 31) g_npairs = off + np;
    int a = -1, w = off, li = 0;
    for (int s = 0; s < BSZ; s++) {
        if (cat_ids[s] == e) {
            g_slist[e][li++] = s;
            if (a < 0) a = s;
            else { g_pairs[w++] = make_int2(a, s); a = -1; }
        }
    }
    if (a >= 0) g_pairs[w++] = make_int2(a, a);
}

// ---------------------------------------------------------------------------
// kF_part: partial F = W1[:, hc*128:+128] @ W2a[hc*128:+128, n-chunk].
// grid (8 n-chunks of 64, EE, 4 h-chunks) = 1024 CTAs. unroll 8 -> high MLP.
// ---------------------------------------------------------------------------
__global__ __launch_bounds__(256) void kF_part(
    const float* __restrict__ W1, const float* __restrict__ W2,
    const float* __restrict__ b1)
{
    const int e = blockIdx.y, hc = blockIdx.z;
    const int n0 = blockIdx.x * 64;
    const int tid = threadIdx.x;
    __shared__ float sW1[AA * 128];   // W1 slab [32][128]
    __shared__ float sb1[128];
    const float* W1e = W1 + (size_t)e * AA * HH + hc * 128;
    for (int i = tid; i < AA * 128 / 4; i += 256) {
        int a = i / 32, q = i % 32;   // 32 float4 per row
        reinterpret_cast<float4*>(sW1)[a * 32 + q] =
            *reinterpret_cast<const float4*>(&W1e[a * HH + q * 4]);
    }
    if (tid < 32)
        reinterpret_cast<float4*>(sb1)[tid] =
            *reinterpret_cast<const float4*>(&b1[e * HH + hc * 128 + tid * 4]);
    __syncthreads();

    const int n = n0 + (tid & 63);
    const int abase = (tid >> 6) * 8;
    const float* W2a = W2 + ((size_t)e * 1024 + hc * 128) * HH + n;

    float acc[8] = {0,0,0,0,0,0,0,0};
    float accC = 0.f;
    #pragma unroll 8
    for (int h = 0; h < 128; h++) {
        float wv = W2a[(size_t)h * HH];
        #pragma unroll
        for (int i = 0; i < 8; i++) acc[i] += sW1[(abase + i) * 128 + h] * wv;
        if (abase == 0) accC += sb1[h] * wv;
    }
    #pragma unroll
    for (int i = 0; i < 8; i++) g_Fp[hc][e][abase + i][n] = acc[i];
    if (abase == 0) g_cp[hc][e][n] = accC;
}

// ---------------------------------------------------------------------------
// k_tauc_part: partial tc over k-chunk of 128. grid (4 n-chunks, EE, 4 k).
// ---------------------------------------------------------------------------
__global__ __launch_bounds__(256) void k_tauc_part(
    const float* __restrict__ W2, const int* __restrict__ timesteps)
{
    const int e = blockIdx.y, kc = blockIdx.z;
    const int n0 = blockIdx.x * 128, tid = threadIdx.x;
    const int cnt = g_scnt[e];
    if (cnt == 0) return;
    const int n = tid & 127, kh = tid >> 7;   // 2 k-sub-halves of 64
    __shared__ float stau[4][128];
    __shared__ float sred[2][4][128];
    const float C = 9.210340371976184f / 256.0f;
    const float* W2t = W2 + ((size_t)e * 1024 + 512 + kc * 128) * HH + n0 + n;

    for (int g0 = 0; g0 < cnt; g0 += 4) {
        const int gc = min(4, cnt - g0);
        for (int idx = tid; idx < gc * 128; idx += 256) {
            int g = idx >> 7, kk = idx & 127;
            int s = g_slist[e][g0 + g];
            float tval = (float)timesteps[s];
            int kidx = kc * 128 + kk;
            int j = kidx & 255;
            float f = tval * expf(-(float)j * C);
            stau[g][kk] = (kidx < 256) ? sinf(f) : cosf(f);
        }
        __syncthreads();
        float acc[4] = {0,0,0,0};
        #pragma unroll 8
        for (int k = kh * 64; k < kh * 64 + 64; k++) {
            float wv = W2t[(size_t)k * HH];
            #pragma unroll
            for (int g = 0; g < 4; g++) acc[g] += stau[g][k] * wv;
        }
        #pragma unroll
        for (int g = 0; g < 4; g++) sred[kh][g][n] = acc[g];
        __syncthreads();
        if (kh == 0)
            for (int g = 0; g < gc; g++) {
                int s = g_slist[e][g0 + g];
                g_tcp[kc][s][n0 + n] = sred[0][g][n] + sred[1][g][n];
            }
        __syncthreads();
    }
}

// ---------------------------------------------------------------------------
// kRed: sum the 4 partials -> g_F, g_c (+b2), g_tc. float4 granularity.
// ---------------------------------------------------------------------------
#define F4COUNT  131072
#define C4COUNT  4096
#define TC4COUNT 32768

__global__ __launch_bounds__(256) void kRed(const float* __restrict__ b2)
{
    const int idx = blockIdx.x * 256 + threadIdx.x;
    if (idx < F4COUNT) {
        const float4* p = reinterpret_cast<const float4*>(&g_Fp[0][0][0][0]);
        float4 a = p[idx], b = p[idx + F4COUNT], c = p[idx + 2 * F4COUNT], d = p[idx + 3 * F4COUNT];
        reinterpret_cast<float4*>(&g_F[0][0][0])[idx] =
            make_float4(a.x + b.x + c.x + d.x, a.y + b.y + c.y + d.y,
                        a.z + b.z + c.z + d.z, a.w + b.w + c.w + d.w);
    } else if (idx < F4COUNT + C4COUNT) {
        const int i = idx - F4COUNT;
        const float4* p = reinterpret_cast<const float4*>(&g_cp[0][0][0]);
        float4 a = p[i], b = p[i + C4COUNT], c = p[i + 2 * C4COUNT], d = p[i + 3 * C4COUNT];
        float4 bb = reinterpret_cast<const float4*>(b2)[i];
        reinterpret_cast<float4*>(&g_c[0][0])[i] =
            make_float4(a.x + b.x + c.x + d.x + bb.x, a.y + b.y + c.y + d.y + bb.y,
                        a.z + b.z + c.z + d.z + bb.z, a.w + b.w + c.w + d.w + bb.w);
    } else {
        const int i = idx - F4COUNT - C4COUNT;
        if (i < TC4COUNT) {
            const float4* p = reinterpret_cast<const float4*>(&g_tcp[0][0][0]);
            float4 a = p[i], b = p[i + TC4COUNT], c = p[i + 2 * TC4COUNT], d = p[i + 3 * TC4COUNT];
            reinterpret_cast<float4*>(&g_tc[0][0])[i] =
                make_float4(a.x + b.x + c.x + d.x, a.y + b.y + c.y + d.y,
                            a.z + b.z + c.z + d.z, a.w + b.w + c.w + d.w);
        }
    }
}

// ---------------------------------------------------------------------------
// k2: y2 = actions@F[e] (K=32) + tc + c; x2 = swish(y2) -> hi/lo bf16 in g_A3
// ---------------------------------------------------------------------------
__global__ __launch_bounds__(256) void k2_mid(
    const float* __restrict__ actions, const int* __restrict__ cat_ids)
{
    const int s = blockIdx.x, tid = threadIdx.x;
    const int tbase = blockIdx.y * 32;
    const int e = cat_ids[s];
    __shared__ float sA[32][36];

    const float* Ab = actions + ((size_t)s * TT + tbase) * AA;
    {
        int row = tid >> 3, c4 = tid & 7;
        float4 v = *reinterpret_cast<const float4*>(&Ab[row * AA + c4 * 4]);
        *reinterpret_cast<float4*>(&sA[row][c4 * 4]) = v;
    }
    __syncthreads();

    const int h0 = 2 * tid;
    float2 w[AA];
    #pragma unroll
    for (int k = 0; k < AA; k++)
        w[k] = *reinterpret_cast<const float2*>(&g_F[e][k][h0]);
    float2 tc = *reinterpret_cast<const float2*>(&g_tc[s][h0]);
    float2 cc = *reinterpret_cast<const float2*>(&g_c[e][h0]);
    const float base0 = tc.x + cc.x, base1 = tc.y + cc.y;

    for (int tl = 0; tl < 32; tl++) {
        float a0 = base0, a1 = base1;
        #pragma unroll
        for (int k = 0; k < AA; k++) {
            float av = sA[tl][k];
            a0 += av * w[k].x; a1 += av * w[k].y;
        }
        a0 = a0 * (1.f / (1.f + expf(-a0)));
        a1 = a1 * (1.f / (1.f + expf(-a1)));
        __nv_bfloat16 hh0 = __float2bfloat16_rn(a0), hh1 = __float2bfloat16_rn(a1);
        __nv_bfloat16 ll0 = __float2bfloat16_rn(a0 - __bfloat162float(hh0));
        __nv_bfloat16 ll1 = __float2bfloat16_rn(a1 - __bfloat162float(hh1));
        __nv_bfloat16* row = &g_A3[s][tbase + tl][0];
        *reinterpret_cast<unsigned*>(row + h0)       = pk(hh0, hh1);
        *reinterpret_cast<unsigned*>(row + 512 + h0) = pk(ll0, ll1);
    }
}

// ---------------------------------------------------------------------------
// Layer-3 GEMM: M=128 (pair) x N=128, 3-stage cp.async, single sync/chunk.
// Stage 64KB: Ahi@0 | Alo@16K | Bhi@32K | Blo@48K. 8 warps, warp tile 64x32.
// ---------------------------------------------------------------------------
#define STAGE_BYTES 65536
#define GSMEM (3 * STAGE_BYTES + 1024)

__global__ __launch_bounds__(256, 1) void gemm3(
    const float* __restrict__ bias, const int* __restrict__ cat_ids,
    float* __restrict__ out)
{
    constexpr int KP  = 512;
    constexpr int TPC = KP / 64;   // 8 chunks

    const int mt_blk = blockIdx.y;
    if (mt_blk >= g_npairs) return;
    const int n0 = blockIdx.x * 128;
    const int2 pr = g_pairs[mt_blk];
    const int s0 = pr.x, s1 = pr.y;
    const int e  = cat_ids[s0];

    extern __shared__ char smem[];
    const uint32_t sb = (smem_u32(smem) + 127) & ~127u;

    const int tid  = threadIdx.x;
    const int wid  = tid >> 5;
    const int lane = tid & 31;
    const int mWarp = (wid >> 2) * 64;   // 0 or 64
    const int nWarp = (wid & 3) * 32;    // 0,32,64,96

    const __nv_bfloat16* aRow[4]; uint32_t dAo[4];
    #pragma unroll
    for (int i = 0; i < 4; i++) {
        int idx = tid + 256 * i;
        int r = idx >> 3, sg = idx & 7;
        int samp = (r < 64) ? s0 : s1;
        aRow[i] = &g_A3[samp][r & 63][0] + sg * 8;
        dAo[i]  = (uint32_t)(r * 128 + ((sg * 16) ^ ((r & 7) * 16)));
    }
    const __nv_bfloat16* bRow[4]; uint32_t dBo[4];
    #pragma unroll
    for (int i = 0; i < 4; i++) {
        int idx = tid + 256 * i;
        int r = idx >> 3, sg = idx & 7;          // r in 0..127
        bRow[i] = &g_B3[e][n0 + r][0] + sg * 8;
        dBo[i]  = (uint32_t)(r * 128 + ((sg * 16) ^ ((r & 7) * 16)));
    }

    auto issue = [&](int c) {
        int pkk = c * 64;
        uint32_t sof = sb + (uint32_t)(c % 3) * STAGE_BYTES;
        #pragma unroll
        for (int i = 0; i < 4; i++) {
            CP_ASYNC16(sof + dAo[i],         aRow[i] + pkk);       // Ahi
            CP_ASYNC16(sof + 16384 + dAo[i], aRow[i] + KP + pkk);  // Alo
        }
        #pragma unroll
        for (int i = 0; i < 4; i++) {
            CP_ASYNC16(sof + 32768 + dBo[i], bRow[i] + pkk);       // Bhi
            CP_ASYNC16(sof + 49152 + dBo[i], bRow[i] + KP + pkk);  // Blo
        }
        CP_COMMIT();
    };

    const uint32_t maskk = (lane & 7) * 16;
    const uint32_t aRowB = (uint32_t)(mWarp + (lane & 7) + ((lane & 8) ? 8 : 0)) * 128;
    const uint32_t kextA = (lane & 16) ? 16 : 0;
    const uint32_t bRowB = (uint32_t)((nWarp + (lane & 7) + ((lane & 16) ? 8 : 0)) * 128);
    const uint32_t kextB = (lane & 8) ? 16 : 0;

    float acc[4][4][4];
    #pragma unroll
    for (int m = 0; m < 4; m++)
        #pragma unroll
        for (int j = 0; j < 4; j++)
            #pragma unroll
            for (int q = 0; q < 4; q++) acc[m][j][q] = 0.f;

    issue(0); issue(1);

    for (int c = 0; c < TPC; c++) {
        if (c + 1 < TPC) { CP_WAIT1(); } else { CP_WAIT0(); }
        __syncthreads();
        if (c + 2 < TPC) issue(c + 2);   // overwrites stage consumed at c-1 (safe post-sync)

        const uint32_t stb = sb + (uint32_t)(c % 3) * STAGE_BYTES;
        #pragma unroll
        for (int ks = 0; ks < 4; ks++) {
            const uint32_t kA = (uint32_t)(ks * 32 + kextA) ^ maskk;
            const uint32_t kB = (uint32_t)(ks * 32 + kextB) ^ maskk;
            uint32_t a[4][4], b[2][4], c2[4][4];
            #pragma unroll
            for (int m = 0; m < 4; m++)
                LDSM_X4(a[m], stb + aRowB + m * 2048 + kA);
            #pragma unroll
            for (int nt = 0; nt < 2; nt++)
                LDSM_X4(b[nt], stb + 32768 + bRowB + nt * 2048 + kB);
            #pragma unroll
            for (int m = 0; m < 4; m++)
                #pragma unroll
                for (int j = 0; j < 4; j++)
                    MMA16816(acc[m][j], a[m], b[j >> 1][(j & 1) * 2], b[j >> 1][(j & 1) * 2 + 1]);
            // Alo * Bhi
            #pragma unroll
            for (int m = 0; m < 4; m++)
                LDSM_X4(c2[m], stb + 16384 + aRowB + m * 2048 + kA);
            #pragma unroll
            for (int m = 0; m < 4; m++)
                #pragma unroll
                for (int j = 0; j < 4; j++)
                    MMA16816(acc[m][j], c2[m], b[j >> 1][(j & 1) * 2], b[j >> 1][(j & 1) * 2 + 1]);
            // Ahi * Blo (reuse first two c2 slots for Blo)
            #pragma unroll
            for (int nt = 0; nt < 2; nt++)
                LDSM_X4(c2[nt], stb + 49152 + bRowB + nt * 2048 + kB);
            #pragma unroll
            for (int m = 0; m < 4; m++)
                #pragma unroll
                for (int j = 0; j < 4; j++)
                    MMA16816(acc[m][j], a[m], c2[j >> 1][(j & 1) * 2], c2[j >> 1][(j & 1) * 2 + 1]);
        }
    }

    const float* biasE = bias + e * HH;
    const int sampW = (mWarp < 64) ? s0 : s1;
    #pragma unroll
    for (int m = 0; m < 4; m++) {
        int rloc = mWarp + m * 16 + (lane >> 2);
        int t0 = rloc & 63, t1 = (rloc + 8) & 63;
        #pragma unroll
        for (int j = 0; j < 4; j++) {
            int cidx = n0 + nWarp + j * 8 + (lane & 3) * 2;
            float2 bv = *reinterpret_cast<const float2*>(&biasE[cidx]);
            float* p0 = out + ((size_t)sampW * TT + t0) * HH + cidx;
            float* p1 = out + ((size_t)sampW * TT + t1) * HH + cidx;
            *reinterpret_cast<float2*>(p0) = make_float2(acc[m][j][0] + bv.x, acc[m][j][1] + bv.y);
            *reinterpret_cast<float2*>(p1) = make_float2(acc[m][j][2] + bv.x, acc[m][j][3] + bv.y);
        }
    }
}

// ---------------------------------------------------------------------------
extern "C" void kernel_launch(void* const* d_in, const int* in_sizes, int n_in,
                              void* d_out, int out_size)
{
    const float* actions   = (const float*)d_in[0];
    const int*   timesteps = (const int*)  d_in[1];
    const int*   cat_ids   = (const int*)  d_in[2];
    const float* W1        = (const float*)d_in[3];
    const float* b1        = (const float*)d_in[4];
    const float* W2        = (const float*)d_in[5];
    const float* b2        = (const float*)d_in[6];
    const float* W3        = (const float*)d_in[7];
    const float* b3        = (const float*)d_in[8];
    float* out = (float*)d_out;

    cudaFuncSetAttribute(gemm3, cudaFuncAttributeMaxDynamicSharedMemorySize, GSMEM);

    conv_w3<<<dim3(16, 16, EE), 256>>>(W3);
    k_pairs<<<1, 32>>>(cat_ids);
    kF_part<<<dim3(8, EE, 4), 256>>>(W1, W2, b1);
    k_tauc_part<<<dim3(4, EE, 4), 256>>>(W2, timesteps);
    kRed<<<656, 256>>>(b2);
    k2_mid<<<dim3(BSZ, 2), 256>>>(actions, cat_ids);
    gemm3<<<dim3(4, 144), 256, GSMEM>>>(b3, cat_ids, out);
}

// round 16
// speedup vs baseline: 2.3318x; 1.0974x over previous
#include <cuda_runtime.h>
#include <cuda_bf16.h>
#include <cstdint>
#include <math.h>

#define BSZ 256
#define TT  64
#define AA  32
#define HH  512
#define EE  32

// -------- device scratch (allocation-free) --------
__device__ __align__(256) __nv_bfloat16 g_B3[EE][HH][1024]; // [e][n][hi(512)|lo(512)]
__device__ __align__(256) __nv_bfloat16 g_A3[BSZ][TT][1024]; // x2 [hi(512)|lo(512)]
__device__ __align__(256) float g_F[EE][AA][HH];    // fused W1@W2a
__device__ __align__(256) float g_c[EE][HH];        // b1@W2a + b2
__device__ __align__(256) float g_tc[BSZ][HH];      // tau @ W2tau
__device__ __align__(256) float g_Fp[4][EE][AA][HH];  // h-chunk partials
__device__ __align__(256) float g_cp[4][EE][HH];
__device__ __align__(256) float g_tcp[4][BSZ][HH];    // k-chunk partials
__device__ int2 g_pairs[160];
__device__ int  g_npairs;
__device__ int  g_scnt[EE];
__device__ int  g_slist[EE][BSZ];

// -------- helpers --------
__device__ __forceinline__ uint32_t smem_u32(const void* p){
    uint32_t a;
    asm("{ .reg .u64 t; cvta.to.shared.u64 t, %1; cvt.u32.u64 %0, t; }" : "=r"(a) : "l"(p));
    return a;
}
__device__ __forceinline__ unsigned pk(__nv_bfloat16 a, __nv_bfloat16 b){
    unsigned short x = *reinterpret_cast<unsigned short*>(&a);
    unsigned short y = *reinterpret_cast<unsigned short*>(&b);
    return (unsigned)x | ((unsigned)y << 16);
}

#define CP_ASYNC16(dst, src) \
    asm volatile("cp.async.cg.shared.global [%0], [%1], 16;" :: "r"(dst), "l"(src))
#define CP_COMMIT() asm volatile("cp.async.commit_group;" ::: "memory")
#define CP_WAIT0()  asm volatile("cp.async.wait_group 0;" ::: "memory")
#define CP_WAIT1()  asm volatile("cp.async.wait_group 1;" ::: "memory")

#define LDSM_X4(r, addr) \
    asm volatile("ldmatrix.sync.aligned.m8n8.x4.shared.b16 {%0,%1,%2,%3}, [%4];" \
        : "=r"((r)[0]), "=r"((r)[1]), "=r"((r)[2]), "=r"((r)[3]) : "r"(addr))

#define MMA16816(d, a, b0, b1) \
    asm volatile("mma.sync.aligned.m16n8k16.row.col.f32.bf16.bf16.f32 " \
        "{%0,%1,%2,%3}, {%4,%5,%6,%7}, {%8,%9}, {%0,%1,%2,%3};" \
        : "+f"((d)[0]), "+f"((d)[1]), "+f"((d)[2]), "+f"((d)[3]) \
        : "r"((a)[0]), "r"((a)[1]), "r"((a)[2]), "r"((a)[3]), "r"(b0), "r"(b1))

// ---------------------------------------------------------------------------
// Pairing + per-expert sample lists (runs first; feeds tauc + gemm3)
// ---------------------------------------------------------------------------
__global__ void k_pairs(const int* __restrict__ cat_ids)
{
    int e = threadIdx.x;  // 32 threads
    int cnt = 0;
    for (int s = 0; s < BSZ; s++) cnt += (cat_ids[s] == e);
    g_scnt[e] = cnt;
    int np = (cnt + 1) >> 1;
    int inc = np;
    for (int d = 1; d < 32; d <<= 1) {
        int v = __shfl_up_sync(0xffffffffu, inc, d);
        if (e >= d) inc += v;
    }
    int off = inc - np;
    if (e == 31) g_npairs = off + np;
    int a = -1, w = off, li = 0;
    for (int s = 0; s < BSZ; s++) {
        if (cat_ids[s] == e) {
            g_slist[e][li++] = s;
            if (a < 0) a = s;
            else { g_pairs[w++] = make_int2(a, s); a = -1; }
        }
    }
    if (a >= 0) g_pairs[w++] = make_int2(a, a);
}

// ---------------------------------------------------------------------------
// fused_pre bodies
// ---------------------------------------------------------------------------
__device__ void tauc_body(int nc, int e, int kc,
    const float* __restrict__ W2, const int* __restrict__ ts, char* sm)
{
    const int cnt = g_scnt[e];
    if (cnt == 0) return;
    const int tid = threadIdx.x;
    const int n = tid & 63, ks = tid >> 6;     // 4 k-quarters of 32
    float* stau = (float*)sm;                  // [8][128]
    float* sred = (float*)(sm + 4096);         // [4][8][64]
    const int n0 = nc * 64;
    const float C = 9.210340371976184f / 256.0f;
    const float* W2t = W2 + ((size_t)e * 1024 + 512 + kc * 128) * HH + n0 + n;

    for (int g0 = 0; g0 < cnt; g0 += 8) {
        const int gc = min(8, cnt - g0);
        __syncthreads();
        for (int idx = tid; idx < gc * 128; idx += 256) {
            int g = idx >> 7, kk = idx & 127;
            int s = g_slist[e][g0 + g];
            float tval = (float)ts[s];
            int kidx = kc * 128 + kk;
            int j = kidx & 255;
            float f = tval * expf(-(float)j * C);
            stau[g * 128 + kk] = (kidx < 256) ? sinf(f) : cosf(f);
        }
        __syncthreads();
        float acc[8] = {0,0,0,0,0,0,0,0};
        #pragma unroll 8
        for (int k = ks * 32; k < ks * 32 + 32; k++) {
            float wv = W2t[(size_t)k * HH];
            #pragma unroll
            for (int g = 0; g < 8; g++) acc[g] += stau[g * 128 + k] * wv;
        }
        #pragma unroll
        for (int g = 0; g < 8; g++) sred[(ks * 8 + g) * 64 + n] = acc[g];
        __syncthreads();
        for (int idx = tid; idx < gc * 64; idx += 256) {
            int g = idx >> 6, nn = idx & 63;
            int s = g_slist[e][g0 + g];
            g_tcp[kc][s][n0 + nn] =
                sred[(0 + g) * 64 + nn] + sred[(8 + g) * 64 + nn] +
                sred[(16 + g) * 64 + nn] + sred[(24 + g) * 64 + nn];
        }
    }
}

__device__ void kF_body(int nc, int e, int hc,
    const float* __restrict__ W1, const float* __restrict__ W2,
    const float* __restrict__ b1, char* sm)
{
    const int n0 = nc * 64;
    const int tid = threadIdx.x;
    float* sW1 = (float*)sm;            // 32*128
    float* sb1 = (float*)(sm + 16384);  // 128
    const float* W1e = W1 + (size_t)e * AA * HH + hc * 128;
    for (int i = tid; i < AA * 128 / 4; i += 256) {
        int a = i / 32, q = i % 32;
        reinterpret_cast<float4*>(sW1)[a * 32 + q] =
            *reinterpret_cast<const float4*>(&W1e[a * HH + q * 4]);
    }
    if (tid < 32)
        reinterpret_cast<float4*>(sb1)[tid] =
            *reinterpret_cast<const float4*>(&b1[e * HH + hc * 128 + tid * 4]);
    __syncthreads();

    const int n = n0 + (tid & 63);
    const int abase = (tid >> 6) * 8;
    const float* W2a = W2 + ((size_t)e * 1024 + hc * 128) * HH + n;

    float acc[8] = {0,0,0,0,0,0,0,0};
    float accC = 0.f;
    #pragma unroll 8
    for (int h = 0; h < 128; h++) {
        float wv = W2a[(size_t)h * HH];
        #pragma unroll
        for (int i = 0; i < 8; i++) acc[i] += sW1[(abase + i) * 128 + h] * wv;
        if (abase == 0) accC += sb1[h] * wv;
    }
    #pragma unroll
    for (int i = 0; i < 8; i++) g_Fp[hc][e][abase + i][n] = acc[i];
    if (abase == 0) g_cp[hc][e][n] = accC;
}

__device__ void conv_body(int kt, int nt, int e,
    const float* __restrict__ W, char* smc)
{
    float (*sm)[33] = (float(*)[33])smc;
    const int k0 = kt * 32, n0 = nt * 32;
    const int tid = threadIdx.x;
    #pragma unroll
    for (int i = 0; i < 4; i++) {
        int idx = tid + i * 256;
        int kk = idx >> 5, nn = idx & 31;
        sm[kk][nn] = W[((size_t)e * HH + k0 + kk) * HH + n0 + nn];
    }
    __syncthreads();
    const int n = tid >> 3, g = tid & 7;
    __nv_bfloat16 hi[4], lo[4];
    #pragma unroll
    for (int j = 0; j < 4; j++) {
        float x = sm[g * 4 + j][n];
        hi[j] = __float2bfloat16_rn(x);
        lo[j] = __float2bfloat16_rn(x - __bfloat162float(hi[j]));
    }
    __nv_bfloat16* dst = &g_B3[e][n0 + n][k0 + g * 4];
    *reinterpret_cast<uint2*>(dst)       = make_uint2(pk(hi[0], hi[1]), pk(hi[2], hi[3]));
    *reinterpret_cast<uint2*>(dst + 512) = make_uint2(pk(lo[0], lo[1]), pk(lo[2], lo[3]));
}

// fused: [0,1024) tauc | [1024,2048) kF | [2048,10240) conv_w3
#define FUSED_CTAS 10240
#define FUSED_SMEM 17408

__global__ __launch_bounds__(256) void fused_pre(
    const float* __restrict__ W1, const float* __restrict__ W2,
    const float* __restrict__ W3, const float* __restrict__ b1,
    const int* __restrict__ timesteps)
{
    extern __shared__ char sm[];
    const int b = blockIdx.x;
    if (b < 1024) {
        int nc = b & 7, e = (b >> 3) & 31, kc = b >> 8;
        tauc_body(nc, e, kc, W2, timesteps, sm);
    } else if (b < 2048) {
        int i = b - 1024;
        int nc = i & 7, e = (i >> 3) & 31, hc = i >> 8;
        kF_body(nc, e, hc, W1, W2, b1, sm);
    } else {
        int i = b - 2048;
        int kt = i & 15, nt = (i >> 4) & 15, e = i >> 8;
        conv_body(kt, nt, e, W3, sm);
    }
}

// ---------------------------------------------------------------------------
// kRed: sum the 4 partials -> g_F, g_c (+b2), g_tc. float4 granularity.
// ---------------------------------------------------------------------------
#define F4COUNT  131072
#define C4COUNT  4096
#define TC4COUNT 32768

__global__ __launch_bounds__(256) void kRed(const float* __restrict__ b2)
{
    const int idx = blockIdx.x * 256 + threadIdx.x;
    if (idx < F4COUNT) {
        const float4* p = reinterpret_cast<const float4*>(&g_Fp[0][0][0][0]);
        float4 a = p[idx], b = p[idx + F4COUNT], c = p[idx + 2 * F4COUNT], d = p[idx + 3 * F4COUNT];
        reinterpret_cast<float4*>(&g_F[0][0][0])[idx] =
            make_float4(a.x + b.x + c.x + d.x, a.y + b.y + c.y + d.y,
                        a.z + b.z + c.z + d.z, a.w + b.w + c.w + d.w);
    } else if (idx < F4COUNT + C4COUNT) {
        const int i = idx - F4COUNT;
        const float4* p = reinterpret_cast<const float4*>(&g_cp[0][0][0]);
        float4 a = p[i], b = p[i + C4COUNT], c = p[i + 2 * C4COUNT], d = p[i + 3 * C4COUNT];
        float4 bb = reinterpret_cast<const float4*>(b2)[i];
        reinterpret_cast<float4*>(&g_c[0][0])[i] =
            make_float4(a.x + b.x + c.x + d.x + bb.x, a.y + b.y + c.y + d.y + bb.y,
                        a.z + b.z + c.z + d.z + bb.z, a.w + b.w + c.w + d.w + bb.w);
    } else {
        const int i = idx - F4COUNT - C4COUNT;
        if (i < TC4COUNT) {
            const float4* p = reinterpret_cast<const float4*>(&g_tcp[0][0][0]);
            float4 a = p[i], b = p[i + TC4COUNT], c = p[i + 2 * TC4COUNT], d = p[i + 3 * TC4COUNT];
            reinterpret_cast<float4*>(&g_tc[0][0])[i] =
                make_float4(a.x + b.x + c.x + d.x, a.y + b.y + c.y + d.y,
                            a.z + b.z + c.z + d.z, a.w + b.w + c.w + d.w);
        }
    }
}

// ---------------------------------------------------------------------------
// k2: y2 = actions@F[e] (K=32) + tc + c; x2 = swish(y2) -> hi/lo bf16 in g_A3
// ---------------------------------------------------------------------------
__global__ __launch_bounds__(256) void k2_mid(
    const float* __restrict__ actions, const int* __restrict__ cat_ids)
{
    const int s = blockIdx.x, tid = threadIdx.x;
    const int tbase = blockIdx.y * 32;
    const int e = cat_ids[s];
    __shared__ float sA[32][36];

    const float* Ab = actions + ((size_t)s * TT + tbase) * AA;
    {
        int row = tid >> 3, c4 = tid & 7;
        float4 v = *reinterpret_cast<const float4*>(&Ab[row * AA + c4 * 4]);
        *reinterpret_cast<float4*>(&sA[row][c4 * 4]) = v;
    }
    __syncthreads();

    const int h0 = 2 * tid;
    float2 w[AA];
    #pragma unroll
    for (int k = 0; k < AA; k++)
        w[k] = *reinterpret_cast<const float2*>(&g_F[e][k][h0]);
    float2 tc = *reinterpret_cast<const float2*>(&g_tc[s][h0]);
    float2 cc = *reinterpret_cast<const float2*>(&g_c[e][h0]);
    const float base0 = tc.x + cc.x, base1 = tc.y + cc.y;

    for (int tl = 0; tl < 32; tl++) {
        float a0 = base0, a1 = base1;
        #pragma unroll
        for (int k = 0; k < AA; k++) {
            float av = sA[tl][k];
            a0 += av * w[k].x; a1 += av * w[k].y;
        }
        a0 = a0 * (1.f / (1.f + expf(-a0)));
        a1 = a1 * (1.f / (1.f + expf(-a1)));
        __nv_bfloat16 hh0 = __float2bfloat16_rn(a0), hh1 = __float2bfloat16_rn(a1);
        __nv_bfloat16 ll0 = __float2bfloat16_rn(a0 - __bfloat162float(hh0));
        __nv_bfloat16 ll1 = __float2bfloat16_rn(a1 - __bfloat162float(hh1));
        __nv_bfloat16* row = &g_A3[s][tbase + tl][0];
        *reinterpret_cast<unsigned*>(row + h0)       = pk(hh0, hh1);
        *reinterpret_cast<unsigned*>(row + 512 + h0) = pk(ll0, ll1);
    }
}

// ---------------------------------------------------------------------------
// Layer-3 GEMM: M=128 (pair) x N=128, 3-stage cp.async, single sync/chunk.
// Stage 64KB: Ahi@0 | Alo@16K | Bhi@32K | Blo@48K. 8 warps, warp tile 64x32.
// ---------------------------------------------------------------------------
#define STAGE_BYTES 65536
#define GSMEM (3 * STAGE_BYTES + 1024)

__global__ __launch_bounds__(256, 1) void gemm3(
    const float* __restrict__ bias, const int* __restrict__ cat_ids,
    float* __restrict__ out)
{
    constexpr int KP  = 512;
    constexpr int TPC = KP / 64;   // 8 chunks

    const int mt_blk = blockIdx.y;
    if (mt_blk >= g_npairs) return;
    const int n0 = blockIdx.x * 128;
    const int2 pr = g_pairs[mt_blk];
    const int s0 = pr.x, s1 = pr.y;
    const int e  = cat_ids[s0];

    extern __shared__ char smem[];
    const uint32_t sb = (smem_u32(smem) + 127) & ~127u;

    const int tid  = threadIdx.x;
    const int wid  = tid >> 5;
    const int lane = tid & 31;
    const int mWarp = (wid >> 2) * 64;   // 0 or 64
    const int nWarp = (wid & 3) * 32;    // 0,32,64,96

    const __nv_bfloat16* aRow[4]; uint32_t dAo[4];
    #pragma unroll
    for (int i = 0; i < 4; i++) {
        int idx = tid + 256 * i;
        int r = idx >> 3, sg = idx & 7;
        int samp = (r < 64) ? s0 : s1;
        aRow[i] = &g_A3[samp][r & 63][0] + sg * 8;
        dAo[i]  = (uint32_t)(r * 128 + ((sg * 16) ^ ((r & 7) * 16)));
    }
    const __nv_bfloat16* bRow[4]; uint32_t dBo[4];
    #pragma unroll
    for (int i = 0; i < 4; i++) {
        int idx = tid + 256 * i;
        int r = idx >> 3, sg = idx & 7;          // r in 0..127
        bRow[i] = &g_B3[e][n0 + r][0] + sg * 8;
        dBo[i]  = (uint32_t)(r * 128 + ((sg * 16) ^ ((r & 7) * 16)));
    }

    auto issue = [&](int c) {
        int pkk = c * 64;
        uint32_t sof = sb + (uint32_t)(c % 3) * STAGE_BYTES;
        #pragma unroll
        for (int i = 0; i < 4; i++) {
            CP_ASYNC16(sof + dAo[i],         aRow[i] + pkk);       // Ahi
            CP_ASYNC16(sof + 16384 + dAo[i], aRow[i] + KP + pkk);  // Alo
        }
        #pragma unroll
        for (int i = 0; i < 4; i++) {
            CP_ASYNC16(sof + 32768 + dBo[i], bRow[i] + pkk);       // Bhi
            CP_ASYNC16(sof + 49152 + dBo[i], bRow[i] + KP + pkk);  // Blo
        }
        CP_COMMIT();
    };

    const uint32_t maskk = (lane & 7) * 16;
    const uint32_t aRowB = (uint32_t)(mWarp + (lane & 7) + ((lane & 8) ? 8 : 0)) * 128;
    const uint32_t kextA = (lane & 16) ? 16 : 0;
    const uint32_t bRowB = (uint32_t)((nWarp + (lane & 7) + ((lane & 16) ? 8 : 0)) * 128);
    const uint32_t kextB = (lane & 8) ? 16 : 0;

    float acc[4][4][4];
    #pragma unroll
    for (int m = 0; m < 4; m++)
        #pragma unroll
        for (int j = 0; j < 4; j++)
            #pragma unroll
            for (int q = 0; q < 4; q++) acc[m][j][q] = 0.f;

    issue(0); issue(1);

    for (int c = 0; c < TPC; c++) {
        if (c + 1 < TPC) { CP_WAIT1(); } else { CP_WAIT0(); }
        __syncthreads();
        if (c + 2 < TPC) issue(c + 2);   // overwrites stage consumed at c-1 (safe post-sync)

        const uint32_t stb = sb + (uint32_t)(c % 3) * STAGE_BYTES;
        #pragma unroll
        for (int ks = 0; ks < 4; ks++) {
            const uint32_t kA = (uint32_t)(ks * 32 + kextA) ^ maskk;
            const uint32_t kB = (uint32_t)(ks * 32 + kextB) ^ maskk;
            uint32_t a[4][4], b[2][4], c2[4][4];
            #pragma unroll
            for (int m = 0; m < 4; m++)
                LDSM_X4(a[m], stb + aRowB + m * 2048 + kA);
            #pragma unroll
            for (int nt = 0; nt < 2; nt++)
                LDSM_X4(b[nt], stb + 32768 + bRowB + nt * 2048 + kB);
            #pragma unroll
            for (int m = 0; m < 4; m++)
                #pragma unroll
                for (int j = 0; j < 4; j++)
                    MMA16816(acc[m][j], a[m], b[j >> 1][(j & 1) * 2], b[j >> 1][(j & 1) * 2 + 1]);
            // Alo * Bhi
            #pragma unroll
            for (int m = 0; m < 4; m++)
                LDSM_X4(c2[m], stb + 16384 + aRowB + m * 2048 + kA);
            #pragma unroll
            for (int m = 0; m < 4; m++)
                #pragma unroll
                for (int j = 0; j < 4; j++)
                    MMA16816(acc[m][j], c2[m], b[j >> 1][(j & 1) * 2], b[j >> 1][(j & 1) * 2 + 1]);
            // Ahi * Blo (reuse first two c2 slots for Blo)
            #pragma unroll
            for (int nt = 0; nt < 2; nt++)
                LDSM_X4(c2[nt], stb + 49152 + bRowB + nt * 2048 + kB);
            #pragma unroll
            for (int m = 0; m < 4; m++)
                #pragma unroll
                for (int j = 0; j < 4; j++)
                    MMA16816(acc[m][j], a[m], c2[j >> 1][(j & 1) * 2], c2[j >> 1][(j & 1) * 2 + 1]);
        }
    }

    const float* biasE = bias + e * HH;
    const int sampW = (mWarp < 64) ? s0 : s1;
    #pragma unroll
    for (int m = 0; m < 4; m++) {
        int rloc = mWarp + m * 16 + (lane >> 2);
        int t0 = rloc & 63, t1 = (rloc + 8) & 63;
        #pragma unroll
        for (int j = 0; j < 4; j++) {
            int cidx = n0 + nWarp + j * 8 + (lane & 3) * 2;
            float2 bv = *reinterpret_cast<const float2*>(&biasE[cidx]);
            float* p0 = out + ((size_t)sampW * TT + t0) * HH + cidx;
            float* p1 = out + ((size_t)sampW * TT + t1) * HH + cidx;
            *reinterpret_cast<float2*>(p0) = make_float2(acc[m][j][0] + bv.x, acc[m][j][1] + bv.y);
            *reinterpret_cast<float2*>(p1) = make_float2(acc[m][j][2] + bv.x, acc[m][j][3] + bv.y);
        }
    }
}

// ---------------------------------------------------------------------------
extern "C" void kernel_launch(void* const* d_in, const int* in_sizes, int n_in,
                              void* d_out, int out_size)
{
    const float* actions   = (const float*)d_in[0];
    const int*   timesteps = (const int*)  d_in[1];
    const int*   cat_ids   = (const int*)  d_in[2];
    const float* W1        = (const float*)d_in[3];
    const float* b1        = (const float*)d_in[4];
    const float* W2        = (const float*)d_in[5];
    const float* b2        = (const float*)d_in[6];
    const float* W3        = (const float*)d_in[7];
    const float* b3        = (const float*)d_in[8];
    float* out = (float*)d_out;

    cudaFuncSetAttribute(gemm3, cudaFuncAttributeMaxDynamicSharedMemorySize, GSMEM);

    k_pairs<<<1, 32>>>(cat_ids);
    fused_pre<<<FUSED_CTAS, 256, FUSED_SMEM>>>(W1, W2, W3, b1, timesteps);
    kRed<<<656, 256>>>(b2);
    k2_mid<<<dim3(BSZ, 2), 256>>>(actions, cat_ids);
    gemm3<<<dim3(4, 144), 256, GSMEM>>>(b3, cat_ids, out);
}